// round 3
// baseline (speedup 1.0000x reference)
#include <cuda_runtime.h>
#include <math.h>
#include <stdint.h>

#define D_MODEL 1024
#define NHEADS  16
#define HD      64
#define NB      4
#define CTX     2048
#define EDIM    (3 * D_MODEL)
#define TOK     (NB * CTX)

// scratch for z = x @ W^T + b : [TOK, 3*D]
__device__ float g_z[(size_t)TOK * EDIM];

__device__ __forceinline__ uint32_t smem_u32(const void* p) {
    return (uint32_t)__cvta_generic_to_shared(p);
}

#define CP_ASYNC16(dst, src) \
    asm volatile("cp.async.ca.shared.global [%0], [%1], 16;\n" :: "r"(dst), "l"(src))
#define CP_COMMIT()  asm volatile("cp.async.commit_group;\n" ::: "memory")
#define CP_WAIT1()   asm volatile("cp.async.wait_group 1;\n" ::: "memory")
#define CP_WAIT0()   asm volatile("cp.async.wait_group 0;\n" ::: "memory")

__device__ __forceinline__ void mma_tf32(float* c, const uint32_t* a, const uint32_t* b) {
    asm volatile(
        "mma.sync.aligned.m16n8k8.row.col.f32.tf32.tf32.f32 "
        "{%0,%1,%2,%3}, {%4,%5,%6,%7}, {%8,%9}, {%0,%1,%2,%3};"
        : "+f"(c[0]), "+f"(c[1]), "+f"(c[2]), "+f"(c[3])
        : "r"(a[0]), "r"(a[1]), "r"(a[2]), "r"(a[3]), "r"(b[0]), "r"(b[1]));
}

// split fp32 into tf32-hi (top 19 bits) and remainder (HW truncates lo to tf32)
__device__ __forceinline__ void split_tf32(float v, uint32_t& hi, uint32_t& lo) {
    uint32_t hb = __float_as_uint(v) & 0xffffe000u;
    hi = hb;
    lo = __float_as_uint(v - __uint_as_float(hb));
}

// ---------------------------------------------------------------------------
// Kernel 1: z[t,e] = sum_k x[t,k] * W[e,k] + b[e]
// TF32 tensor-core GEMM with hi/lo error correction (fp32-equivalent accuracy).
// 128x128x16 block tile, 8 warps (2x4), warp tile 64x32, cp.async double buffer.
// ---------------------------------------------------------------------------
#define BM  128
#define BN  128
#define BKG 16
#define PADR 20   // floats per smem row (16 data + 4 pad)

__global__ __launch_bounds__(256) void qkv_gemm_tc(const float* __restrict__ x,
                                                   const float* __restrict__ W,
                                                   const float* __restrict__ bias) {
    __shared__ float As[2][BM * PADR];
    __shared__ float Bs[2][BN * PADR];

    const int tid  = threadIdx.x;
    const int lane = tid & 31;
    const int warp = tid >> 5;
    const int g    = lane >> 2;      // 0..7
    const int tig  = lane & 3;       // 0..3
    const int wm   = warp >> 2;      // 0..1  -> 64 rows
    const int wn   = warp & 3;       // 0..3  -> 32 cols
    const int t0   = blockIdx.y * BM;
    const int e0   = blockIdx.x * BN;

    float acc[4][4][4];
#pragma unroll
    for (int a = 0; a < 4; a++)
#pragma unroll
        for (int bq = 0; bq < 4; bq++)
#pragma unroll
            for (int c = 0; c < 4; c++) acc[a][bq][c] = 0.f;

    const int NIT = D_MODEL / BKG;   // 64

    auto issue_loads = [&](int it, int buf) {
        const int k0 = it * BKG;
#pragma unroll
        for (int rep = 0; rep < 2; rep++) {
            const int idx = tid + rep * 256;
            const int row = idx >> 2;
            const int kq  = (idx & 3) << 2;
            CP_ASYNC16(smem_u32(&As[buf][row * PADR + kq]),
                       &x[(size_t)(t0 + row) * D_MODEL + k0 + kq]);
            CP_ASYNC16(smem_u32(&Bs[buf][row * PADR + kq]),
                       &W[(size_t)(e0 + row) * D_MODEL + k0 + kq]);
        }
    };

    issue_loads(0, 0);
    CP_COMMIT();

    for (int it = 0; it < NIT; it++) {
        const int cur = it & 1;
        if (it + 1 < NIT) {
            issue_loads(it + 1, cur ^ 1);
            CP_COMMIT();
            CP_WAIT1();
        } else {
            CP_WAIT0();
        }
        __syncthreads();

#pragma unroll
        for (int ks = 0; ks < 2; ks++) {
            const int kb = ks * 8;
            uint32_t ah[4][4], al[4][4];
#pragma unroll
            for (int mi = 0; mi < 4; mi++) {
                const int m0 = wm * 64 + mi * 16 + g;
                float v0 = As[cur][(m0)     * PADR + kb + tig];
                float v1 = As[cur][(m0 + 8) * PADR + kb + tig];
                float v2 = As[cur][(m0)     * PADR + kb + tig + 4];
                float v3 = As[cur][(m0 + 8) * PADR + kb + tig + 4];
                split_tf32(v0, ah[mi][0], al[mi][0]);
                split_tf32(v1, ah[mi][1], al[mi][1]);
                split_tf32(v2, ah[mi][2], al[mi][2]);
                split_tf32(v3, ah[mi][3], al[mi][3]);
            }
#pragma unroll
            for (int ni = 0; ni < 4; ni++) {
                const int n0 = wn * 32 + ni * 8 + g;
                float w0 = Bs[cur][n0 * PADR + kb + tig];
                float w1 = Bs[cur][n0 * PADR + kb + tig + 4];
                uint32_t bh[2], bl[2];
                split_tf32(w0, bh[0], bl[0]);
                split_tf32(w1, bh[1], bl[1]);
#pragma unroll
                for (int mi = 0; mi < 4; mi++) {
                    mma_tf32(acc[mi][ni], ah[mi], bh);
                    mma_tf32(acc[mi][ni], al[mi], bh);
                    mma_tf32(acc[mi][ni], ah[mi], bl);
                }
            }
        }
        __syncthreads();
    }

#pragma unroll
    for (int mi = 0; mi < 4; mi++) {
        const int m = t0 + wm * 64 + mi * 16 + g;
#pragma unroll
        for (int ni = 0; ni < 4; ni++) {
            const int e = e0 + wn * 32 + ni * 8 + 2 * tig;
            const float b0 = bias[e], b1 = bias[e + 1];
            float2 r0, r1;
            r0.x = acc[mi][ni][0] + b0;
            r0.y = acc[mi][ni][1] + b1;
            r1.x = acc[mi][ni][2] + b0;
            r1.y = acc[mi][ni][3] + b1;
            *(float2*)&g_z[(size_t)m * EDIM + e]       = r0;
            *(float2*)&g_z[(size_t)(m + 8) * EDIM + e] = r1;
        }
    }
}

// ---------------------------------------------------------------------------
// Kernel 2: causal attention, flash style, 2 lanes per query row.
// Block = 256 threads = 128 query rows x 2 lanes; each lane owns 32 of 64 dims.
// QK dot reduced across the lane pair via shfl_xor with PAIR-LOCAL mask
// (full-warp mask would deadlock: trip counts diverge across the warp).
// ---------------------------------------------------------------------------
__global__ __launch_bounds__(256) void attn_kernel(float* __restrict__ out) {
    __shared__ float Ks[64][HD];
    __shared__ float Vs[64][HD];

    const int qb   = blockIdx.x;
    const int h    = blockIdx.y;
    const int n    = blockIdx.z;
    const int tid  = threadIdx.x;
    const int lane = tid & 31;
    const int r    = tid >> 1;       // query row within block, 0..127
    const int half = tid & 1;        // which 32-dim half this lane owns
    const int i    = qb * 128 + r;

    const uint32_t pair_mask = 0x3u << (lane & 30);  // the converged lane pair

    const float scale = 1.0f / 32.0f;  // D_MODEL^-0.5, exact

    float q[32], o[32];
    {
        const float* zq = &g_z[((size_t)(n * CTX + i)) * EDIM + D_MODEL + h * HD + half * 32];
#pragma unroll
        for (int d4 = 0; d4 < 8; d4++) {
            float4 v = *(const float4*)&zq[d4 * 4];
            q[d4 * 4 + 0] = v.x * scale;
            q[d4 * 4 + 1] = v.y * scale;
            q[d4 * 4 + 2] = v.z * scale;
            q[d4 * 4 + 3] = v.w * scale;
        }
    }
#pragma unroll
    for (int d = 0; d < 32; d++) o[d] = 0.f;
    float m = -1e30f, l = 0.f;

    const int ntiles = qb * 2 + 2;
    for (int jt = 0; jt < ntiles; jt++) {
        __syncthreads();
        {
            const float* zk = &g_z[((size_t)(n * CTX + jt * 64)) * EDIM + h * HD];
            const float* zv = zk + 2 * D_MODEL;
#pragma unroll
            for (int s = tid; s < 1024; s += 256) {
                const int rr = s >> 4, c4 = (s & 15) * 4;
                *(float4*)&Ks[rr][c4] = *(const float4*)&zk[(size_t)rr * EDIM + c4];
                *(float4*)&Vs[rr][c4] = *(const float4*)&zv[(size_t)rr * EDIM + c4];
            }
        }
        __syncthreads();

        const int lim = min(64, i - jt * 64 + 1);
        for (int jj = 0; jj < lim; jj++) {
            float s = 0.f;
            const float4* k4 = (const float4*)&Ks[jj][half * 32];
#pragma unroll
            for (int d4 = 0; d4 < 8; d4++) {
                float4 kv = k4[d4];
                s += q[d4 * 4 + 0] * kv.x;
                s += q[d4 * 4 + 1] * kv.y;
                s += q[d4 * 4 + 2] * kv.z;
                s += q[d4 * 4 + 3] * kv.w;
            }
            s += __shfl_xor_sync(pair_mask, s, 1);

            if (s > m) {  // lazy rescale (rare); both lanes of a pair agree
                const float corr = __expf(m - s);
                m = s;
                l *= corr;
#pragma unroll
                for (int d = 0; d < 32; d++) o[d] *= corr;
            }
            const float p = __expf(s - m);
            l += p;
            const float4* v4 = (const float4*)&Vs[jj][half * 32];
#pragma unroll
            for (int d4 = 0; d4 < 8; d4++) {
                float4 vv = v4[d4];
                o[d4 * 4 + 0] += p * vv.x;
                o[d4 * 4 + 1] += p * vv.y;
                o[d4 * 4 + 2] += p * vv.z;
                o[d4 * 4 + 3] += p * vv.w;
            }
        }
    }

    const float inv = 1.f / l;
    float* op = &out[((size_t)(n * CTX + i)) * D_MODEL + h * HD + half * 32];
#pragma unroll
    for (int d4 = 0; d4 < 8; d4++) {
        float4 w;
        w.x = o[d4 * 4 + 0] * inv;
        w.y = o[d4 * 4 + 1] * inv;
        w.z = o[d4 * 4 + 2] * inv;
        w.w = o[d4 * 4 + 3] * inv;
        *(float4*)&op[d4 * 4] = w;
    }
}

extern "C" void kernel_launch(void* const* d_in, const int* in_sizes, int n_in,
                              void* d_out, int out_size) {
    const float* x = (const float*)d_in[0];
    const float* W = (const float*)d_in[1];
    const float* b = (const float*)d_in[2];
    float* out = (float*)d_out;

    dim3 g1(EDIM / BN, TOK / BM);     // 24 x 64
    qkv_gemm_tc<<<g1, 256>>>(x, W, b);

    dim3 g2(CTX / 128, NHEADS, NB);   // 16 x 16 x 4
    attn_kernel<<<g2, 256>>>(out);
}

// round 4
// speedup vs baseline: 2.5286x; 2.5286x over previous
#include <cuda_runtime.h>
#include <math.h>
#include <stdint.h>

#define D_MODEL 1024
#define NHEADS  16
#define HD      64
#define NB      4
#define CTX     2048
#define EDIM    (3 * D_MODEL)
#define TOK     (NB * CTX)

// scratch for z = x @ W^T + b : [TOK, 3*D]
__device__ float g_z[(size_t)TOK * EDIM];

__device__ __forceinline__ uint32_t smem_u32(const void* p) {
    return (uint32_t)__cvta_generic_to_shared(p);
}

#define CP_ASYNC16(dst, src) \
    asm volatile("cp.async.ca.shared.global [%0], [%1], 16;\n" :: "r"(dst), "l"(src))
#define CP_COMMIT()  asm volatile("cp.async.commit_group;\n" ::: "memory")
#define CP_WAIT1()   asm volatile("cp.async.wait_group 1;\n" ::: "memory")
#define CP_WAIT0()   asm volatile("cp.async.wait_group 0;\n" ::: "memory")

__device__ __forceinline__ void mma_tf32(float* c, const uint32_t* a, const uint32_t* b) {
    asm volatile(
        "mma.sync.aligned.m16n8k8.row.col.f32.tf32.tf32.f32 "
        "{%0,%1,%2,%3}, {%4,%5,%6,%7}, {%8,%9}, {%0,%1,%2,%3};"
        : "+f"(c[0]), "+f"(c[1]), "+f"(c[2]), "+f"(c[3])
        : "r"(a[0]), "r"(a[1]), "r"(a[2]), "r"(a[3]), "r"(b[0]), "r"(b[1]));
}

__device__ __forceinline__ void split_tf32(float v, uint32_t& hi, uint32_t& lo) {
    uint32_t hb = __float_as_uint(v) & 0xffffe000u;
    hi = hb;
    lo = __float_as_uint(v - __uint_as_float(hb));
}

__device__ __forceinline__ uint32_t cvt_rna_tf32(float v) {
    uint32_t u;
    asm("cvt.rna.tf32.f32 %0, %1;" : "=r"(u) : "f"(v));
    return u;
}

// ---------------------------------------------------------------------------
// Kernel 1: TF32 tensor-core GEMM with hi/lo error correction (unchanged, R3).
// ---------------------------------------------------------------------------
#define BM  128
#define BN  128
#define BKG 16
#define PADR 20

__global__ __launch_bounds__(256) void qkv_gemm_tc(const float* __restrict__ x,
                                                   const float* __restrict__ W,
                                                   const float* __restrict__ bias) {
    __shared__ float As[2][BM * PADR];
    __shared__ float Bs[2][BN * PADR];

    const int tid  = threadIdx.x;
    const int lane = tid & 31;
    const int warp = tid >> 5;
    const int g    = lane >> 2;
    const int tig  = lane & 3;
    const int wm   = warp >> 2;
    const int wn   = warp & 3;
    const int t0   = blockIdx.y * BM;
    const int e0   = blockIdx.x * BN;

    float acc[4][4][4];
#pragma unroll
    for (int a = 0; a < 4; a++)
#pragma unroll
        for (int bq = 0; bq < 4; bq++)
#pragma unroll
            for (int c = 0; c < 4; c++) acc[a][bq][c] = 0.f;

    const int NIT = D_MODEL / BKG;

    auto issue_loads = [&](int it, int buf) {
        const int k0 = it * BKG;
#pragma unroll
        for (int rep = 0; rep < 2; rep++) {
            const int idx = tid + rep * 256;
            const int row = idx >> 2;
            const int kq  = (idx & 3) << 2;
            CP_ASYNC16(smem_u32(&As[buf][row * PADR + kq]),
                       &x[(size_t)(t0 + row) * D_MODEL + k0 + kq]);
            CP_ASYNC16(smem_u32(&Bs[buf][row * PADR + kq]),
                       &W[(size_t)(e0 + row) * D_MODEL + k0 + kq]);
        }
    };

    issue_loads(0, 0);
    CP_COMMIT();

    for (int it = 0; it < NIT; it++) {
        const int cur = it & 1;
        if (it + 1 < NIT) {
            issue_loads(it + 1, cur ^ 1);
            CP_COMMIT();
            CP_WAIT1();
        } else {
            CP_WAIT0();
        }
        __syncthreads();

#pragma unroll
        for (int ks = 0; ks < 2; ks++) {
            const int kb = ks * 8;
            uint32_t ah[4][4], al[4][4];
#pragma unroll
            for (int mi = 0; mi < 4; mi++) {
                const int m0 = wm * 64 + mi * 16 + g;
                float v0 = As[cur][(m0)     * PADR + kb + tig];
                float v1 = As[cur][(m0 + 8) * PADR + kb + tig];
                float v2 = As[cur][(m0)     * PADR + kb + tig + 4];
                float v3 = As[cur][(m0 + 8) * PADR + kb + tig + 4];
                split_tf32(v0, ah[mi][0], al[mi][0]);
                split_tf32(v1, ah[mi][1], al[mi][1]);
                split_tf32(v2, ah[mi][2], al[mi][2]);
                split_tf32(v3, ah[mi][3], al[mi][3]);
            }
#pragma unroll
            for (int ni = 0; ni < 4; ni++) {
                const int n0 = wn * 32 + ni * 8 + g;
                float w0 = Bs[cur][n0 * PADR + kb + tig];
                float w1 = Bs[cur][n0 * PADR + kb + tig + 4];
                uint32_t bh[2], bl[2];
                split_tf32(w0, bh[0], bl[0]);
                split_tf32(w1, bh[1], bl[1]);
#pragma unroll
                for (int mi = 0; mi < 4; mi++) {
                    mma_tf32(acc[mi][ni], ah[mi], bh);
                    mma_tf32(acc[mi][ni], al[mi], bh);
                    mma_tf32(acc[mi][ni], ah[mi], bl);
                }
            }
        }
        __syncthreads();
    }

#pragma unroll
    for (int mi = 0; mi < 4; mi++) {
        const int m = t0 + wm * 64 + mi * 16 + g;
#pragma unroll
        for (int ni = 0; ni < 4; ni++) {
            const int e = e0 + wn * 32 + ni * 8 + 2 * tig;
            const float b0 = bias[e], b1 = bias[e + 1];
            float2 r0, r1;
            r0.x = acc[mi][ni][0] + b0;
            r0.y = acc[mi][ni][1] + b1;
            r1.x = acc[mi][ni][2] + b0;
            r1.y = acc[mi][ni][3] + b1;
            *(float2*)&g_z[(size_t)m * EDIM + e]       = r0;
            *(float2*)&g_z[(size_t)(m + 8) * EDIM + e] = r1;
        }
    }
}

// ---------------------------------------------------------------------------
// Kernel 2: tensor-core flash attention.
// Block = 128 threads (4 warps) = 64 query rows of one (n,h). Warp w owns rows
// [w*16, w*16+16). K/V tiles 64x64 in dyn smem (double buffered, cp.async).
// S = Q K^T via 1x TF32 mma; P*V via 3-mma hi/lo TF32 (fp32-grade accuracy).
// ---------------------------------------------------------------------------
#define PAD   76                    // 76 % 32 == 12: conflict-free frag loads
#define KVF   (64 * PAD)            // floats per K or V tile buffer
#define OFF_K0 0
#define OFF_V0 (KVF)
#define OFF_K1 (2 * KVF)
#define OFF_V1 (3 * KVF)
#define OFF_PB (4 * KVF)            // 4 warps x 16 x PAD
#define ATTN_SMEM_FLOATS (OFF_PB + 4 * 16 * PAD)
#define ATTN_SMEM_BYTES  (ATTN_SMEM_FLOATS * 4)

__global__ __launch_bounds__(128) void attn_tc(float* __restrict__ out) {
    extern __shared__ float sm[];

    const int qb   = (int)gridDim.x - 1 - (int)blockIdx.x;  // big blocks first
    const int h    = blockIdx.y;
    const int n    = blockIdx.z;
    const int tid  = threadIdx.x;
    const int lane = tid & 31;
    const int warp = tid >> 5;
    const int g    = lane >> 2;       // 0..7
    const int tig  = lane & 3;        // 0..3

    const int i0 = qb * 64 + warp * 16;   // warp's first query row
    const float scale = 1.0f / 32.0f;     // D_MODEL^-0.5

    float* Pb = &sm[OFF_PB + warp * 16 * PAD];

    // ---- Q fragments (rows i0+g, i0+g+8), pre-scaled, cvt.rna -> tf32 ----
    uint32_t qa[8][4];
    {
        const float* zq = &g_z[((size_t)(n * CTX)) * EDIM + D_MODEL + h * HD];
        const float* r0 = &zq[(size_t)(i0 + g) * EDIM];
        const float* r1 = &zq[(size_t)(i0 + g + 8) * EDIM];
#pragma unroll
        for (int ks = 0; ks < 8; ks++) {
            qa[ks][0] = cvt_rna_tf32(r0[ks * 8 + tig] * scale);
            qa[ks][1] = cvt_rna_tf32(r1[ks * 8 + tig] * scale);
            qa[ks][2] = cvt_rna_tf32(r0[ks * 8 + tig + 4] * scale);
            qa[ks][3] = cvt_rna_tf32(r1[ks * 8 + tig + 4] * scale);
        }
    }

    float oacc[8][4];
#pragma unroll
    for (int nt = 0; nt < 8; nt++)
#pragma unroll
        for (int c = 0; c < 4; c++) oacc[nt][c] = 0.f;
    float m0 = -1e30f, m1 = -1e30f, l0 = 0.f, l1 = 0.f;

    const int ntiles = qb + 1;

    auto load_tile = [&](int jt, int buf) {
        const float* zk = &g_z[((size_t)(n * CTX + jt * 64)) * EDIM + h * HD];
        const float* zv = zk + 2 * D_MODEL;
        float* Kd = &sm[buf ? OFF_K1 : OFF_K0];
        float* Vd = &sm[buf ? OFF_V1 : OFF_V0];
#pragma unroll
        for (int u = 0; u < 8; u++) {
            const int idx = tid + u * 128;      // 0..1023
            const int row = idx >> 4;
            const int c4  = (idx & 15) * 4;
            CP_ASYNC16(smem_u32(&Kd[row * PAD + c4]), &zk[(size_t)row * EDIM + c4]);
            CP_ASYNC16(smem_u32(&Vd[row * PAD + c4]), &zv[(size_t)row * EDIM + c4]);
        }
    };

    load_tile(0, 0);
    CP_COMMIT();

    for (int jt = 0; jt < ntiles; jt++) {
        const int buf = jt & 1;
        if (jt + 1 < ntiles) {
            load_tile(jt + 1, buf ^ 1);
            CP_COMMIT();
            CP_WAIT1();
        } else {
            CP_WAIT0();
        }
        __syncthreads();

        const float* Ks = &sm[buf ? OFF_K1 : OFF_K0];
        const float* Vs = &sm[buf ? OFF_V1 : OFF_V0];

        // ---- S = Q K^T  (S is 16 x 64 per warp) ----
        float sc[8][4];
#pragma unroll
        for (int nt = 0; nt < 8; nt++) {
            float a4[4] = {0.f, 0.f, 0.f, 0.f};
#pragma unroll
            for (int ks = 0; ks < 8; ks++) {
                uint32_t b[2];
                b[0] = __float_as_uint(Ks[(nt * 8 + g) * PAD + ks * 8 + tig]) & 0xffffe000u;
                b[1] = __float_as_uint(Ks[(nt * 8 + g) * PAD + ks * 8 + tig + 4]) & 0xffffe000u;
                mma_tf32(a4, qa[ks], b);
            }
            sc[nt][0] = a4[0]; sc[nt][1] = a4[1]; sc[nt][2] = a4[2]; sc[nt][3] = a4[3];
        }

        // ---- causal mask (diagonal tile only) ----
        if (jt == qb) {
            const int r0 = i0 + g, r1 = i0 + g + 8;
#pragma unroll
            for (int nt = 0; nt < 8; nt++) {
                const int j = jt * 64 + nt * 8 + 2 * tig;
                if (j     > r0) sc[nt][0] = -INFINITY;
                if (j + 1 > r0) sc[nt][1] = -INFINITY;
                if (j     > r1) sc[nt][2] = -INFINITY;
                if (j + 1 > r1) sc[nt][3] = -INFINITY;
            }
        }

        // ---- online softmax (rows g and g+8) ----
        float mx0 = -INFINITY, mx1 = -INFINITY;
#pragma unroll
        for (int nt = 0; nt < 8; nt++) {
            mx0 = fmaxf(mx0, fmaxf(sc[nt][0], sc[nt][1]));
            mx1 = fmaxf(mx1, fmaxf(sc[nt][2], sc[nt][3]));
        }
        mx0 = fmaxf(mx0, __shfl_xor_sync(0xffffffffu, mx0, 1));
        mx0 = fmaxf(mx0, __shfl_xor_sync(0xffffffffu, mx0, 2));
        mx1 = fmaxf(mx1, __shfl_xor_sync(0xffffffffu, mx1, 1));
        mx1 = fmaxf(mx1, __shfl_xor_sync(0xffffffffu, mx1, 2));

        const float mn0 = fmaxf(m0, mx0);
        const float mn1 = fmaxf(m1, mx1);
        const float c0 = __expf(m0 - mn0);
        const float c1 = __expf(m1 - mn1);
        m0 = mn0; m1 = mn1;

        float rs0 = 0.f, rs1 = 0.f;
#pragma unroll
        for (int nt = 0; nt < 8; nt++) {
            float p00 = __expf(sc[nt][0] - mn0);
            float p01 = __expf(sc[nt][1] - mn0);
            float p10 = __expf(sc[nt][2] - mn1);
            float p11 = __expf(sc[nt][3] - mn1);
            rs0 += p00 + p01;
            rs1 += p10 + p11;
            *(float2*)&Pb[(g)     * PAD + nt * 8 + 2 * tig] = make_float2(p00, p01);
            *(float2*)&Pb[(g + 8) * PAD + nt * 8 + 2 * tig] = make_float2(p10, p11);
        }
        rs0 += __shfl_xor_sync(0xffffffffu, rs0, 1);
        rs0 += __shfl_xor_sync(0xffffffffu, rs0, 2);
        rs1 += __shfl_xor_sync(0xffffffffu, rs1, 1);
        rs1 += __shfl_xor_sync(0xffffffffu, rs1, 2);
        l0 = l0 * c0 + rs0;
        l1 = l1 * c1 + rs1;

        // rescale O
#pragma unroll
        for (int nt = 0; nt < 8; nt++) {
            oacc[nt][0] *= c0; oacc[nt][1] *= c0;
            oacc[nt][2] *= c1; oacc[nt][3] *= c1;
        }

        __syncwarp();

        // ---- O += P V  (3-mma hi/lo) ----
#pragma unroll
        for (int ks = 0; ks < 8; ks++) {
            uint32_t ah[4], al[4];
            split_tf32(Pb[(g)     * PAD + ks * 8 + tig],     ah[0], al[0]);
            split_tf32(Pb[(g + 8) * PAD + ks * 8 + tig],     ah[1], al[1]);
            split_tf32(Pb[(g)     * PAD + ks * 8 + tig + 4], ah[2], al[2]);
            split_tf32(Pb[(g + 8) * PAD + ks * 8 + tig + 4], ah[3], al[3]);
#pragma unroll
            for (int nt = 0; nt < 8; nt++) {
                uint32_t bh[2], bl[2];
                split_tf32(Vs[(ks * 8 + tig)     * PAD + nt * 8 + g], bh[0], bl[0]);
                split_tf32(Vs[(ks * 8 + tig + 4) * PAD + nt * 8 + g], bh[1], bl[1]);
                mma_tf32(oacc[nt], ah, bh);
                mma_tf32(oacc[nt], al, bh);
                mma_tf32(oacc[nt], ah, bl);
            }
        }

        __syncthreads();   // all warps done with Ks/Vs before next prefetch overwrite
    }

    // ---- epilogue ----
    const float inv0 = 1.f / l0;
    const float inv1 = 1.f / l1;
    float* o0 = &out[((size_t)(n * CTX + i0 + g))     * D_MODEL + h * HD];
    float* o1 = &out[((size_t)(n * CTX + i0 + g + 8)) * D_MODEL + h * HD];
#pragma unroll
    for (int nt = 0; nt < 8; nt++) {
        *(float2*)&o0[nt * 8 + 2 * tig] = make_float2(oacc[nt][0] * inv0, oacc[nt][1] * inv0);
        *(float2*)&o1[nt * 8 + 2 * tig] = make_float2(oacc[nt][2] * inv1, oacc[nt][3] * inv1);
    }
}

extern "C" void kernel_launch(void* const* d_in, const int* in_sizes, int n_in,
                              void* d_out, int out_size) {
    const float* x = (const float*)d_in[0];
    const float* W = (const float*)d_in[1];
    const float* b = (const float*)d_in[2];
    float* out = (float*)d_out;

    dim3 g1(EDIM / BN, TOK / BM);
    qkv_gemm_tc<<<g1, 256>>>(x, W, b);

    cudaFuncSetAttribute(attn_tc, cudaFuncAttributeMaxDynamicSharedMemorySize,
                         ATTN_SMEM_BYTES);
    dim3 g2(CTX / 64, NHEADS, NB);    // 32 x 16 x 4
    attn_tc<<<g2, 128, ATTN_SMEM_BYTES>>>(out);
}

// round 5
// speedup vs baseline: 2.6705x; 1.0561x over previous
#include <cuda_runtime.h>
#include <cuda_bf16.h>
#include <math.h>
#include <stdint.h>

#define D_MODEL 1024
#define NHEADS  16
#define HD      64
#define NB      4
#define CTX     2048
#define EDIM    (3 * D_MODEL)
#define TOK     (NB * CTX)

__device__ float g_z[(size_t)TOK * EDIM];

__device__ __forceinline__ uint32_t smem_u32(const void* p) {
    return (uint32_t)__cvta_generic_to_shared(p);
}

#define CP_ASYNC16(dst, src) \
    asm volatile("cp.async.ca.shared.global [%0], [%1], 16;\n" :: "r"(dst), "l"(src))
#define CP_COMMIT()  asm volatile("cp.async.commit_group;\n" ::: "memory")
#define CP_WAIT1()   asm volatile("cp.async.wait_group 1;\n" ::: "memory")
#define CP_WAIT0()   asm volatile("cp.async.wait_group 0;\n" ::: "memory")

__device__ __forceinline__ void mma_tf32(float* c, const uint32_t* a, const uint32_t* b) {
    asm volatile(
        "mma.sync.aligned.m16n8k8.row.col.f32.tf32.tf32.f32 "
        "{%0,%1,%2,%3}, {%4,%5,%6,%7}, {%8,%9}, {%0,%1,%2,%3};"
        : "+f"(c[0]), "+f"(c[1]), "+f"(c[2]), "+f"(c[3])
        : "r"(a[0]), "r"(a[1]), "r"(a[2]), "r"(a[3]), "r"(b[0]), "r"(b[1]));
}

__device__ __forceinline__ void mma_bf16(float* c, const uint32_t* a, const uint32_t* b) {
    asm volatile(
        "mma.sync.aligned.m16n8k16.row.col.f32.bf16.bf16.f32 "
        "{%0,%1,%2,%3}, {%4,%5,%6,%7}, {%8,%9}, {%0,%1,%2,%3};"
        : "+f"(c[0]), "+f"(c[1]), "+f"(c[2]), "+f"(c[3])
        : "r"(a[0]), "r"(a[1]), "r"(a[2]), "r"(a[3]), "r"(b[0]), "r"(b[1]));
}

// pack (a,b) into bf16x2 hi + bf16x2 lo (residual); a -> low 16 bits.
__device__ __forceinline__ void split_bf16x2(float a, float b, uint32_t& hi, uint32_t& lo) {
    __nv_bfloat162 h = __floats2bfloat162_rn(a, b);
    float ra = a - __low2float(h);
    float rb = b - __high2float(h);
    __nv_bfloat162 l = __floats2bfloat162_rn(ra, rb);
    hi = *reinterpret_cast<uint32_t*>(&h);
    lo = *reinterpret_cast<uint32_t*>(&l);
}

__device__ __forceinline__ uint32_t cvt_rna_tf32(float v) {
    uint32_t u;
    asm("cvt.rna.tf32.f32 %0, %1;" : "=r"(u) : "f"(v));
    return u;
}

// ---------------------------------------------------------------------------
// Kernel 1: z = x @ W^T + b, bf16x2 double-double GEMM (3x m16n8k16 per K16).
// 128x128x16 block tile, 8 warps, warp tile 64x32, cp.async double buffer.
// ---------------------------------------------------------------------------
#define BM  128
#define BN  128
#define BKG 16
#define PADR 20

__global__ __launch_bounds__(256) void qkv_gemm_tc(const float* __restrict__ x,
                                                   const float* __restrict__ W,
                                                   const float* __restrict__ bias) {
    __shared__ float As[2][BM * PADR];
    __shared__ float Bs[2][BN * PADR];

    const int tid  = threadIdx.x;
    const int lane = tid & 31;
    const int warp = tid >> 5;
    const int g    = lane >> 2;
    const int tig  = lane & 3;
    const int wm   = warp >> 2;
    const int wn   = warp & 3;
    const int t0   = blockIdx.y * BM;
    const int e0   = blockIdx.x * BN;

    float acc[4][4][4];
#pragma unroll
    for (int a = 0; a < 4; a++)
#pragma unroll
        for (int bq = 0; bq < 4; bq++)
#pragma unroll
            for (int c = 0; c < 4; c++) acc[a][bq][c] = 0.f;

    const int NIT = D_MODEL / BKG;   // 64

    auto issue_loads = [&](int it, int buf) {
        const int k0 = it * BKG;
#pragma unroll
        for (int rep = 0; rep < 2; rep++) {
            const int idx = tid + rep * 256;
            const int row = idx >> 2;
            const int kq  = (idx & 3) << 2;
            CP_ASYNC16(smem_u32(&As[buf][row * PADR + kq]),
                       &x[(size_t)(t0 + row) * D_MODEL + k0 + kq]);
            CP_ASYNC16(smem_u32(&Bs[buf][row * PADR + kq]),
                       &W[(size_t)(e0 + row) * D_MODEL + k0 + kq]);
        }
    };

    issue_loads(0, 0);
    CP_COMMIT();

    for (int it = 0; it < NIT; it++) {
        const int cur = it & 1;
        if (it + 1 < NIT) {
            issue_loads(it + 1, cur ^ 1);
            CP_COMMIT();
            CP_WAIT1();
        } else {
            CP_WAIT0();
        }
        __syncthreads();

        uint32_t ah[4][4], al[4][4];
#pragma unroll
        for (int mi = 0; mi < 4; mi++) {
            const int m0 = wm * 64 + mi * 16 + g;
            const float* ra = &As[cur][m0 * PADR];
            const float* rb = &As[cur][(m0 + 8) * PADR];
            split_bf16x2(ra[2 * tig],     ra[2 * tig + 1], ah[mi][0], al[mi][0]);
            split_bf16x2(rb[2 * tig],     rb[2 * tig + 1], ah[mi][1], al[mi][1]);
            split_bf16x2(ra[2 * tig + 8], ra[2 * tig + 9], ah[mi][2], al[mi][2]);
            split_bf16x2(rb[2 * tig + 8], rb[2 * tig + 9], ah[mi][3], al[mi][3]);
        }
#pragma unroll
        for (int ni = 0; ni < 4; ni++) {
            const int n0 = wn * 32 + ni * 8 + g;
            const float* rn = &Bs[cur][n0 * PADR];
            uint32_t bh[2], bl[2];
            split_bf16x2(rn[2 * tig],     rn[2 * tig + 1], bh[0], bl[0]);
            split_bf16x2(rn[2 * tig + 8], rn[2 * tig + 9], bh[1], bl[1]);
#pragma unroll
            for (int mi = 0; mi < 4; mi++) {
                mma_bf16(acc[mi][ni], ah[mi], bh);
                mma_bf16(acc[mi][ni], al[mi], bh);
                mma_bf16(acc[mi][ni], ah[mi], bl);
            }
        }
        __syncthreads();
    }

#pragma unroll
    for (int mi = 0; mi < 4; mi++) {
        const int m = t0 + wm * 64 + mi * 16 + g;
#pragma unroll
        for (int ni = 0; ni < 4; ni++) {
            const int e = e0 + wn * 32 + ni * 8 + 2 * tig;
            const float b0 = bias[e], b1 = bias[e + 1];
            float2 r0, r1;
            r0.x = acc[mi][ni][0] + b0;
            r0.y = acc[mi][ni][1] + b1;
            r1.x = acc[mi][ni][2] + b0;
            r1.y = acc[mi][ni][3] + b1;
            *(float2*)&g_z[(size_t)m * EDIM + e]       = r0;
            *(float2*)&g_z[(size_t)(m + 8) * EDIM + e] = r1;
        }
    }
}

// ---------------------------------------------------------------------------
// Kernel 2: tensor-core flash attention, 8 warps = 128 query rows per CTA.
// S = Q K^T: single-pass TF32 mma.  P V: bf16x2 3-mma (double-double), with
// P fragments taken DIRECTLY from softmax registers (C-frag pair == bf16
// A-frag k-pair) — no P smem round trip.
// ---------------------------------------------------------------------------
#define PAD   76
#define KVF   (64 * PAD)
#define OFF_K0 0
#define OFF_V0 (KVF)
#define OFF_K1 (2 * KVF)
#define OFF_V1 (3 * KVF)
#define ATTN_SMEM_BYTES (4 * KVF * 4)

__global__ __launch_bounds__(256) void attn_tc(float* __restrict__ out) {
    extern __shared__ float sm[];

    const int qb   = (int)gridDim.x - 1 - (int)blockIdx.x;  // big blocks first
    const int h    = blockIdx.y;
    const int n    = blockIdx.z;
    const int tid  = threadIdx.x;
    const int lane = tid & 31;
    const int warp = tid >> 5;
    const int g    = lane >> 2;
    const int tig  = lane & 3;

    const int i0 = qb * 128 + warp * 16;
    const float scale = 1.0f / 32.0f;

    // ---- Q fragments (rows i0+g, i0+g+8), pre-scaled, tf32 ----
    uint32_t qa[8][4];
    {
        const float* zq = &g_z[((size_t)(n * CTX)) * EDIM + D_MODEL + h * HD];
        const float* r0 = &zq[(size_t)(i0 + g) * EDIM];
        const float* r1 = &zq[(size_t)(i0 + g + 8) * EDIM];
#pragma unroll
        for (int ks = 0; ks < 8; ks++) {
            qa[ks][0] = cvt_rna_tf32(r0[ks * 8 + tig] * scale);
            qa[ks][1] = cvt_rna_tf32(r1[ks * 8 + tig] * scale);
            qa[ks][2] = cvt_rna_tf32(r0[ks * 8 + tig + 4] * scale);
            qa[ks][3] = cvt_rna_tf32(r1[ks * 8 + tig + 4] * scale);
        }
    }

    float oacc[8][4];
#pragma unroll
    for (int nt = 0; nt < 8; nt++)
#pragma unroll
        for (int c = 0; c < 4; c++) oacc[nt][c] = 0.f;
    float m0 = -1e30f, m1 = -1e30f, l0 = 0.f, l1 = 0.f;

    const int ntiles   = qb * 2 + 2;
    const int my_tiles = qb * 2 + 1 + (warp >> 2);  // warps 0-3 skip last tile

    auto load_tile = [&](int jt, int buf) {
        const float* zk = &g_z[((size_t)(n * CTX + jt * 64)) * EDIM + h * HD];
        const float* zv = zk + 2 * D_MODEL;
        float* Kd = &sm[buf ? OFF_K1 : OFF_K0];
        float* Vd = &sm[buf ? OFF_V1 : OFF_V0];
#pragma unroll
        for (int u = 0; u < 4; u++) {
            const int idx = tid + u * 256;      // 0..1023
            const int row = idx >> 4;
            const int c4  = (idx & 15) * 4;
            CP_ASYNC16(smem_u32(&Kd[row * PAD + c4]), &zk[(size_t)row * EDIM + c4]);
            CP_ASYNC16(smem_u32(&Vd[row * PAD + c4]), &zv[(size_t)row * EDIM + c4]);
        }
    };

    load_tile(0, 0);
    CP_COMMIT();

    for (int jt = 0; jt < ntiles; jt++) {
        const int buf = jt & 1;
        if (jt + 1 < ntiles) {
            load_tile(jt + 1, buf ^ 1);
            CP_COMMIT();
            CP_WAIT1();
        } else {
            CP_WAIT0();
        }
        __syncthreads();

        if (jt < my_tiles) {
            const float* Ks = &sm[buf ? OFF_K1 : OFF_K0];
            const float* Vs = &sm[buf ? OFF_V1 : OFF_V0];

            // ---- S = Q K^T (16 x 64 per warp) ----
            float sc[8][4];
#pragma unroll
            for (int nt = 0; nt < 8; nt++) {
                float a4[4] = {0.f, 0.f, 0.f, 0.f};
#pragma unroll
                for (int ks = 0; ks < 8; ks++) {
                    uint32_t b[2];
                    b[0] = __float_as_uint(Ks[(nt * 8 + g) * PAD + ks * 8 + tig]) & 0xffffe000u;
                    b[1] = __float_as_uint(Ks[(nt * 8 + g) * PAD + ks * 8 + tig + 4]) & 0xffffe000u;
                    mma_tf32(a4, qa[ks], b);
                }
                sc[nt][0] = a4[0]; sc[nt][1] = a4[1]; sc[nt][2] = a4[2]; sc[nt][3] = a4[3];
            }

            // ---- causal mask on this warp's diagonal tile ----
            if (jt == my_tiles - 1) {
                const int r0 = i0 + g, r1 = i0 + g + 8;
#pragma unroll
                for (int nt = 0; nt < 8; nt++) {
                    const int j = jt * 64 + nt * 8 + 2 * tig;
                    if (j     > r0) sc[nt][0] = -INFINITY;
                    if (j + 1 > r0) sc[nt][1] = -INFINITY;
                    if (j     > r1) sc[nt][2] = -INFINITY;
                    if (j + 1 > r1) sc[nt][3] = -INFINITY;
                }
            }

            // ---- online softmax ----
            float mx0 = -INFINITY, mx1 = -INFINITY;
#pragma unroll
            for (int nt = 0; nt < 8; nt++) {
                mx0 = fmaxf(mx0, fmaxf(sc[nt][0], sc[nt][1]));
                mx1 = fmaxf(mx1, fmaxf(sc[nt][2], sc[nt][3]));
            }
            mx0 = fmaxf(mx0, __shfl_xor_sync(0xffffffffu, mx0, 1));
            mx0 = fmaxf(mx0, __shfl_xor_sync(0xffffffffu, mx0, 2));
            mx1 = fmaxf(mx1, __shfl_xor_sync(0xffffffffu, mx1, 1));
            mx1 = fmaxf(mx1, __shfl_xor_sync(0xffffffffu, mx1, 2));

            const float mn0 = fmaxf(m0, mx0);
            const float mn1 = fmaxf(m1, mx1);
            const float c0 = __expf(m0 - mn0);
            const float c1 = __expf(m1 - mn1);
            m0 = mn0; m1 = mn1;

            float rs0 = 0.f, rs1 = 0.f;
#pragma unroll
            for (int nt = 0; nt < 8; nt++) {
                sc[nt][0] = __expf(sc[nt][0] - mn0);
                sc[nt][1] = __expf(sc[nt][1] - mn0);
                sc[nt][2] = __expf(sc[nt][2] - mn1);
                sc[nt][3] = __expf(sc[nt][3] - mn1);
                rs0 += sc[nt][0] + sc[nt][1];
                rs1 += sc[nt][2] + sc[nt][3];
            }
            rs0 += __shfl_xor_sync(0xffffffffu, rs0, 1);
            rs0 += __shfl_xor_sync(0xffffffffu, rs0, 2);
            rs1 += __shfl_xor_sync(0xffffffffu, rs1, 1);
            rs1 += __shfl_xor_sync(0xffffffffu, rs1, 2);
            l0 = l0 * c0 + rs0;
            l1 = l1 * c1 + rs1;

#pragma unroll
            for (int nt = 0; nt < 8; nt++) {
                oacc[nt][0] *= c0; oacc[nt][1] *= c0;
                oacc[nt][2] *= c1; oacc[nt][3] *= c1;
            }

            // ---- O += P V (bf16x2 3-mma; P frags straight from sc regs) ----
#pragma unroll
            for (int ks = 0; ks < 4; ks++) {
                uint32_t ah[4], al[4];
                // a0/a1: k = 16ks + {2tig,2tig+1}, rows g / g+8  -> sc[2ks]
                split_bf16x2(sc[2 * ks][0],     sc[2 * ks][1],     ah[0], al[0]);
                split_bf16x2(sc[2 * ks][2],     sc[2 * ks][3],     ah[1], al[1]);
                // a2/a3: k = 16ks + 8 + {2tig,2tig+1}            -> sc[2ks+1]
                split_bf16x2(sc[2 * ks + 1][0], sc[2 * ks + 1][1], ah[2], al[2]);
                split_bf16x2(sc[2 * ks + 1][2], sc[2 * ks + 1][3], ah[3], al[3]);
#pragma unroll
                for (int nt = 0; nt < 8; nt++) {
                    const int col = nt * 8 + g;
                    uint32_t bh[2], bl[2];
                    split_bf16x2(Vs[(16 * ks + 2 * tig)     * PAD + col],
                                 Vs[(16 * ks + 2 * tig + 1) * PAD + col], bh[0], bl[0]);
                    split_bf16x2(Vs[(16 * ks + 2 * tig + 8) * PAD + col],
                                 Vs[(16 * ks + 2 * tig + 9) * PAD + col], bh[1], bl[1]);
                    mma_bf16(oacc[nt], ah, bh);
                    mma_bf16(oacc[nt], al, bh);
                    mma_bf16(oacc[nt], ah, bl);
                }
            }
        }

        __syncthreads();   // all warps done with Ks/Vs before next overwrite
    }

    // ---- epilogue ----
    const float inv0 = 1.f / l0;
    const float inv1 = 1.f / l1;
    float* o0 = &out[((size_t)(n * CTX + i0 + g))     * D_MODEL + h * HD];
    float* o1 = &out[((size_t)(n * CTX + i0 + g + 8)) * D_MODEL + h * HD];
#pragma unroll
    for (int nt = 0; nt < 8; nt++) {
        *(float2*)&o0[nt * 8 + 2 * tig] = make_float2(oacc[nt][0] * inv0, oacc[nt][1] * inv0);
        *(float2*)&o1[nt * 8 + 2 * tig] = make_float2(oacc[nt][2] * inv1, oacc[nt][3] * inv1);
    }
}

extern "C" void kernel_launch(void* const* d_in, const int* in_sizes, int n_in,
                              void* d_out, int out_size) {
    const float* x = (const float*)d_in[0];
    const float* W = (const float*)d_in[1];
    const float* b = (const float*)d_in[2];
    float* out = (float*)d_out;

    dim3 g1(EDIM / BN, TOK / BM);
    qkv_gemm_tc<<<g1, 256>>>(x, W, b);

    cudaFuncSetAttribute(attn_tc, cudaFuncAttributeMaxDynamicSharedMemorySize,
                         ATTN_SMEM_BYTES);
    dim3 g2(CTX / 128, NHEADS, NB);   // 16 x 16 x 4
    attn_tc<<<g2, 256, ATTN_SMEM_BYTES>>>(out);
}

// round 7
// speedup vs baseline: 3.4514x; 1.2924x over previous
#include <cuda_runtime.h>
#include <cuda_bf16.h>
#include <math.h>
#include <stdint.h>

#define D_MODEL 1024
#define NHEADS  16
#define HD      64
#define NB      4
#define CTX     2048
#define EDIM    (3 * D_MODEL)
#define TOK     (NB * CTX)

__device__ float g_z[(size_t)TOK * EDIM];
// pre-split bf16 hi/lo copies of x and W
__device__ __nv_bfloat16 g_xh[(size_t)TOK * D_MODEL];
__device__ __nv_bfloat16 g_xl[(size_t)TOK * D_MODEL];
__device__ __nv_bfloat16 g_wh[(size_t)EDIM * D_MODEL];
__device__ __nv_bfloat16 g_wl[(size_t)EDIM * D_MODEL];

__device__ __forceinline__ uint32_t smem_u32(const void* p) {
    return (uint32_t)__cvta_generic_to_shared(p);
}

#define CP_ASYNC16(dst, src) \
    asm volatile("cp.async.ca.shared.global [%0], [%1], 16;\n" :: "r"(dst), "l"(src))
#define CP_COMMIT()  asm volatile("cp.async.commit_group;\n" ::: "memory")
#define CP_WAIT1()   asm volatile("cp.async.wait_group 1;\n" ::: "memory")
#define CP_WAIT0()   asm volatile("cp.async.wait_group 0;\n" ::: "memory")

__device__ __forceinline__ void mma_tf32(float* c, const uint32_t* a, const uint32_t* b) {
    asm volatile(
        "mma.sync.aligned.m16n8k8.row.col.f32.tf32.tf32.f32 "
        "{%0,%1,%2,%3}, {%4,%5,%6,%7}, {%8,%9}, {%0,%1,%2,%3};"
        : "+f"(c[0]), "+f"(c[1]), "+f"(c[2]), "+f"(c[3])
        : "r"(a[0]), "r"(a[1]), "r"(a[2]), "r"(a[3]), "r"(b[0]), "r"(b[1]));
}

__device__ __forceinline__ void mma_bf16(float* c, const uint32_t* a, const uint32_t* b) {
    asm volatile(
        "mma.sync.aligned.m16n8k16.row.col.f32.bf16.bf16.f32 "
        "{%0,%1,%2,%3}, {%4,%5,%6,%7}, {%8,%9}, {%0,%1,%2,%3};"
        : "+f"(c[0]), "+f"(c[1]), "+f"(c[2]), "+f"(c[3])
        : "r"(a[0]), "r"(a[1]), "r"(a[2]), "r"(a[3]), "r"(b[0]), "r"(b[1]));
}

__device__ __forceinline__ void split_bf16x2(float a, float b, uint32_t& hi, uint32_t& lo) {
    __nv_bfloat162 h = __floats2bfloat162_rn(a, b);
    float ra = a - __low2float(h);
    float rb = b - __high2float(h);
    __nv_bfloat162 l = __floats2bfloat162_rn(ra, rb);
    hi = *reinterpret_cast<uint32_t*>(&h);
    lo = *reinterpret_cast<uint32_t*>(&l);
}

__device__ __forceinline__ uint32_t cvt_rna_tf32(float v) {
    uint32_t u;
    asm("cvt.rna.tf32.f32 %0, %1;" : "=r"(u) : "f"(v));
    return u;
}

// ---------------------------------------------------------------------------
// Kernel 0: split fp32 -> bf16 hi + bf16 lo (residual). sel: 0 = x, 1 = W.
// ---------------------------------------------------------------------------
__global__ __launch_bounds__(256) void presplit_k(const float* __restrict__ src,
                                                  int sel, int n4) {
    int i = blockIdx.x * 256 + threadIdx.x;
    if (i >= n4) return;
    float4 v = ((const float4*)src)[i];
    __nv_bfloat162 h0 = __floats2bfloat162_rn(v.x, v.y);
    __nv_bfloat162 l0 = __floats2bfloat162_rn(v.x - __low2float(h0), v.y - __high2float(h0));
    __nv_bfloat162 h1 = __floats2bfloat162_rn(v.z, v.w);
    __nv_bfloat162 l1 = __floats2bfloat162_rn(v.z - __low2float(h1), v.w - __high2float(h1));
    uint2 H, L;
    H.x = *reinterpret_cast<uint32_t*>(&h0);
    H.y = *reinterpret_cast<uint32_t*>(&h1);
    L.x = *reinterpret_cast<uint32_t*>(&l0);
    L.y = *reinterpret_cast<uint32_t*>(&l1);
    if (sel == 0) {
        ((uint2*)g_xh)[i] = H;
        ((uint2*)g_xl)[i] = L;
    } else {
        ((uint2*)g_wh)[i] = H;
        ((uint2*)g_wl)[i] = L;
    }
}

// ---------------------------------------------------------------------------
// Kernel 1: z = x @ W^T + b, bf16 3-term mma.sync GEMM on PRE-SPLIT operands.
// Inner loop: pure LDS.32 + mma (no conversion math).
// 128x128 tile, 8 warps (warp tile 64x32), K chunks of 32, double buffered.
// smem rows: 32 bf16 data + 8 pad = 40 bf16 = 20 u32 -> conflict-free frags.
// ---------------------------------------------------------------------------
#define GROW32  20                 // uint32 per smem row
#define GTILEB  (128 * GROW32 * 4) // 10240 bytes per tile
#define GBUFB   (4 * GTILEB)       // Ah, Al, Bh, Bl
#define GEMM_SMEM_BYTES (2 * GBUFB)
#define G_NCH   (D_MODEL / 32)     // 32 chunks

__global__ __launch_bounds__(256, 2) void qkv_gemm_bf(const float* __restrict__ bias) {
    extern __shared__ char smg[];
    const uint32_t sb = smem_u32(smg);

    const int tid  = threadIdx.x;
    const int lane = tid & 31;
    const int warp = tid >> 5;
    const int g    = lane >> 2;
    const int tig  = lane & 3;
    const int wm   = warp >> 2;
    const int wn   = warp & 3;
    const int t0   = blockIdx.y * 128;
    const int e0   = blockIdx.x * 128;

    float acc[4][4][4];
#pragma unroll
    for (int a = 0; a < 4; a++)
#pragma unroll
        for (int bq = 0; bq < 4; bq++)
#pragma unroll
            for (int c = 0; c < 4; c++) acc[a][bq][c] = 0.f;

    auto load_chunk = [&](int ch, int buf) {
        const __nv_bfloat16* s0 = g_xh + (size_t)t0 * D_MODEL + ch * 32;
        const __nv_bfloat16* s1 = g_xl + (size_t)t0 * D_MODEL + ch * 32;
        const __nv_bfloat16* s2 = g_wh + (size_t)e0 * D_MODEL + ch * 32;
        const __nv_bfloat16* s3 = g_wl + (size_t)e0 * D_MODEL + ch * 32;
        const __nv_bfloat16* srcs[4] = {s0, s1, s2, s3};
        const uint32_t bb = sb + buf * GBUFB;
#pragma unroll
        for (int u = 0; u < 8; u++) {
            const int idx = tid + u * 256;       // 0..2047
            const int t   = idx >> 9;            // tile 0..3
            const int r   = idx & 511;
            const int row = r >> 2;              // 0..127
            const int seg = r & 3;               // 16B segment
            CP_ASYNC16(bb + t * GTILEB + row * 80 + seg * 16,
                       srcs[t] + (size_t)row * D_MODEL + seg * 8);
        }
    };

    load_chunk(0, 0);
    CP_COMMIT();

    for (int it = 0; it < G_NCH; it++) {
        const int buf = it & 1;
        if (it + 1 < G_NCH) {
            load_chunk(it + 1, buf ^ 1);
            CP_COMMIT();
            CP_WAIT1();
        } else {
            CP_WAIT0();
        }
        __syncthreads();

        const uint32_t* Ah = (const uint32_t*)(smg + buf * GBUFB);
        const uint32_t* Al = Ah + GTILEB / 4;
        const uint32_t* Bh = Al + GTILEB / 4;
        const uint32_t* Bl = Bh + GTILEB / 4;

#pragma unroll
        for (int ks = 0; ks < 2; ks++) {
            const int kb = ks * 8 + tig;
            uint32_t ah[4][4], al[4][4];
#pragma unroll
            for (int mi = 0; mi < 4; mi++) {
                const int m0 = (wm * 64 + mi * 16 + g) * GROW32;
                ah[mi][0] = Ah[m0 + kb];
                ah[mi][1] = Ah[m0 + 8 * GROW32 + kb];
                ah[mi][2] = Ah[m0 + kb + 4];
                ah[mi][3] = Ah[m0 + 8 * GROW32 + kb + 4];
                al[mi][0] = Al[m0 + kb];
                al[mi][1] = Al[m0 + 8 * GROW32 + kb];
                al[mi][2] = Al[m0 + kb + 4];
                al[mi][3] = Al[m0 + 8 * GROW32 + kb + 4];
            }
#pragma unroll
            for (int ni = 0; ni < 4; ni++) {
                const int n0 = (wn * 32 + ni * 8 + g) * GROW32;
                uint32_t bh[2], bl[2];
                bh[0] = Bh[n0 + kb];
                bh[1] = Bh[n0 + kb + 4];
                bl[0] = Bl[n0 + kb];
                bl[1] = Bl[n0 + kb + 4];
#pragma unroll
                for (int mi = 0; mi < 4; mi++) {
                    mma_bf16(acc[mi][ni], ah[mi], bh);
                    mma_bf16(acc[mi][ni], al[mi], bh);
                    mma_bf16(acc[mi][ni], ah[mi], bl);
                }
            }
        }
        __syncthreads();
    }

#pragma unroll
    for (int mi = 0; mi < 4; mi++) {
        const int m = t0 + wm * 64 + mi * 16 + g;
#pragma unroll
        for (int ni = 0; ni < 4; ni++) {
            const int e = e0 + wn * 32 + ni * 8 + 2 * tig;
            const float b0 = bias[e], b1 = bias[e + 1];
            float2 r0, r1;
            r0.x = acc[mi][ni][0] + b0;
            r0.y = acc[mi][ni][1] + b1;
            r1.x = acc[mi][ni][2] + b0;
            r1.y = acc[mi][ni][3] + b1;
            *(float2*)&g_z[(size_t)m * EDIM + e]       = r0;
            *(float2*)&g_z[(size_t)(m + 8) * EDIM + e] = r1;
        }
    }
}

// ---------------------------------------------------------------------------
// Kernel 2: tensor-core flash attention. NEW: cooperative V pre-convert to
// bf16 hi/lo TRANSPOSED smem (one pass per tile per CTA, amortized over all
// 8 warps); PV B-fragments become two LDS.32 each.
// ---------------------------------------------------------------------------
#define PAD   76
#define KVF   (64 * PAD)
#define OFF_K0 0
#define OFF_V0 (KVF)
#define OFF_K1 (2 * KVF)
#define OFF_V1 (3 * KVF)
#define VTROW  41                   // uint32 per transposed col (32 + 9 pad)
#define VTSZ   (64 * VTROW)         // u32 per V-transposed array
#define OFF_VT (4 * KVF)            // u32 index base: [Vth0][Vtl0][Vth1][Vtl1]
#define ATTN_SMEM_BYTES ((4 * KVF + 4 * VTSZ) * 4)

__global__ __launch_bounds__(256) void attn_tc(float* __restrict__ out) {
    extern __shared__ float sm[];
    uint32_t* smu = (uint32_t*)sm;

    const int qb   = (int)gridDim.x - 1 - (int)blockIdx.x;
    const int h    = blockIdx.y;
    const int n    = blockIdx.z;
    const int tid  = threadIdx.x;
    const int lane = tid & 31;
    const int warp = tid >> 5;
    const int g    = lane >> 2;
    const int tig  = lane & 3;

    const int i0 = qb * 128 + warp * 16;
    const float scale = 1.0f / 32.0f;

    uint32_t qa[8][4];
    {
        const float* zq = &g_z[((size_t)(n * CTX)) * EDIM + D_MODEL + h * HD];
        const float* r0 = &zq[(size_t)(i0 + g) * EDIM];
        const float* r1 = &zq[(size_t)(i0 + g + 8) * EDIM];
#pragma unroll
        for (int ks = 0; ks < 8; ks++) {
            qa[ks][0] = cvt_rna_tf32(r0[ks * 8 + tig] * scale);
            qa[ks][1] = cvt_rna_tf32(r1[ks * 8 + tig] * scale);
            qa[ks][2] = cvt_rna_tf32(r0[ks * 8 + tig + 4] * scale);
            qa[ks][3] = cvt_rna_tf32(r1[ks * 8 + tig + 4] * scale);
        }
    }

    float oacc[8][4];
#pragma unroll
    for (int nt = 0; nt < 8; nt++)
#pragma unroll
        for (int c = 0; c < 4; c++) oacc[nt][c] = 0.f;
    float m0 = -1e30f, m1 = -1e30f, l0 = 0.f, l1 = 0.f;

    const int ntiles   = qb * 2 + 2;
    const int my_tiles = qb * 2 + 1 + (warp >> 2);

    auto load_tile = [&](int jt, int buf) {
        const float* zk = &g_z[((size_t)(n * CTX + jt * 64)) * EDIM + h * HD];
        const float* zv = zk + 2 * D_MODEL;
        float* Kd = &sm[buf ? OFF_K1 : OFF_K0];
        float* Vd = &sm[buf ? OFF_V1 : OFF_V0];
#pragma unroll
        for (int u = 0; u < 4; u++) {
            const int idx = tid + u * 256;
            const int row = idx >> 4;
            const int c4  = (idx & 15) * 4;
            CP_ASYNC16(smem_u32(&Kd[row * PAD + c4]), &zk[(size_t)row * EDIM + c4]);
            CP_ASYNC16(smem_u32(&Vd[row * PAD + c4]), &zv[(size_t)row * EDIM + c4]);
        }
    };

    load_tile(0, 0);
    CP_COMMIT();

    for (int jt = 0; jt < ntiles; jt++) {
        const int buf = jt & 1;
        if (jt + 1 < ntiles) {
            load_tile(jt + 1, buf ^ 1);
            CP_COMMIT();
            CP_WAIT1();
        } else {
            CP_WAIT0();
        }
        __syncthreads();

        const float* Ks = &sm[buf ? OFF_K1 : OFF_K0];
        const float* Vs = &sm[buf ? OFF_V1 : OFF_V0];
        uint32_t* Vth = smu + OFF_VT + buf * 2 * VTSZ;
        uint32_t* Vtl = Vth + VTSZ;

        // ---- cooperative V convert: fp32 [k][col] -> bf16 hi/lo [col][kpair] ----
#pragma unroll
        for (int u = 0; u < 8; u++) {
            const int idx = tid + u * 256;     // 0..2047
            const int col = idx & 63;
            const int kp  = idx >> 6;          // k-pair 0..31
            uint32_t hi, lo;
            split_bf16x2(Vs[(2 * kp) * PAD + col], Vs[(2 * kp + 1) * PAD + col], hi, lo);
            Vth[col * VTROW + kp] = hi;
            Vtl[col * VTROW + kp] = lo;
        }
        __syncthreads();

        if (jt < my_tiles) {
            // ---- S = Q K^T ----
            float sc[8][4];
#pragma unroll
            for (int nt = 0; nt < 8; nt++) {
                float a4[4] = {0.f, 0.f, 0.f, 0.f};
#pragma unroll
                for (int ks = 0; ks < 8; ks++) {
                    uint32_t b[2];
                    b[0] = __float_as_uint(Ks[(nt * 8 + g) * PAD + ks * 8 + tig]) & 0xffffe000u;
                    b[1] = __float_as_uint(Ks[(nt * 8 + g) * PAD + ks * 8 + tig + 4]) & 0xffffe000u;
                    mma_tf32(a4, qa[ks], b);
                }
                sc[nt][0] = a4[0]; sc[nt][1] = a4[1]; sc[nt][2] = a4[2]; sc[nt][3] = a4[3];
            }

            if (jt == my_tiles - 1) {
                const int r0 = i0 + g, r1 = i0 + g + 8;
#pragma unroll
                for (int nt = 0; nt < 8; nt++) {
                    const int j = jt * 64 + nt * 8 + 2 * tig;
                    if (j     > r0) sc[nt][0] = -INFINITY;
                    if (j + 1 > r0) sc[nt][1] = -INFINITY;
                    if (j     > r1) sc[nt][2] = -INFINITY;
                    if (j + 1 > r1) sc[nt][3] = -INFINITY;
                }
            }

            // ---- online softmax ----
            float mx0 = -INFINITY, mx1 = -INFINITY;
#pragma unroll
            for (int nt = 0; nt < 8; nt++) {
                mx0 = fmaxf(mx0, fmaxf(sc[nt][0], sc[nt][1]));
                mx1 = fmaxf(mx1, fmaxf(sc[nt][2], sc[nt][3]));
            }
            mx0 = fmaxf(mx0, __shfl_xor_sync(0xffffffffu, mx0, 1));
            mx0 = fmaxf(mx0, __shfl_xor_sync(0xffffffffu, mx0, 2));
            mx1 = fmaxf(mx1, __shfl_xor_sync(0xffffffffu, mx1, 1));
            mx1 = fmaxf(mx1, __shfl_xor_sync(0xffffffffu, mx1, 2));

            const float mn0 = fmaxf(m0, mx0);
            const float mn1 = fmaxf(m1, mx1);
            const float c0 = __expf(m0 - mn0);
            const float c1 = __expf(m1 - mn1);
            m0 = mn0; m1 = mn1;

            float rs0 = 0.f, rs1 = 0.f;
#pragma unroll
            for (int nt = 0; nt < 8; nt++) {
                sc[nt][0] = __expf(sc[nt][0] - mn0);
                sc[nt][1] = __expf(sc[nt][1] - mn0);
                sc[nt][2] = __expf(sc[nt][2] - mn1);
                sc[nt][3] = __expf(sc[nt][3] - mn1);
                rs0 += sc[nt][0] + sc[nt][1];
                rs1 += sc[nt][2] + sc[nt][3];
            }
            rs0 += __shfl_xor_sync(0xffffffffu, rs0, 1);
            rs0 += __shfl_xor_sync(0xffffffffu, rs0, 2);
            rs1 += __shfl_xor_sync(0xffffffffu, rs1, 1);
            rs1 += __shfl_xor_sync(0xffffffffu, rs1, 2);
            l0 = l0 * c0 + rs0;
            l1 = l1 * c1 + rs1;

#pragma unroll
            for (int nt = 0; nt < 8; nt++) {
                oacc[nt][0] *= c0; oacc[nt][1] *= c0;
                oacc[nt][2] *= c1; oacc[nt][3] *= c1;
            }

            // ---- O += P V  (bf16x2 3-mma; V frags via 2x LDS.32) ----
#pragma unroll
            for (int ks = 0; ks < 4; ks++) {
                uint32_t ah[4], al[4];
                split_bf16x2(sc[2 * ks][0],     sc[2 * ks][1],     ah[0], al[0]);
                split_bf16x2(sc[2 * ks][2],     sc[2 * ks][3],     ah[1], al[1]);
                split_bf16x2(sc[2 * ks + 1][0], sc[2 * ks + 1][1], ah[2], al[2]);
                split_bf16x2(sc[2 * ks + 1][2], sc[2 * ks + 1][3], ah[3], al[3]);
#pragma unroll
                for (int nt = 0; nt < 8; nt++) {
                    const uint32_t* vh = &Vth[(nt * 8 + g) * VTROW + 8 * ks + tig];
                    const uint32_t* vl = &Vtl[(nt * 8 + g) * VTROW + 8 * ks + tig];
                    uint32_t bh[2] = {vh[0], vh[4]};
                    uint32_t bl[2] = {vl[0], vl[4]};
                    mma_bf16(oacc[nt], ah, bh);
                    mma_bf16(oacc[nt], al, bh);
                    mma_bf16(oacc[nt], ah, bl);
                }
            }
        }

        __syncthreads();
    }

    const float inv0 = 1.f / l0;
    const float inv1 = 1.f / l1;
    float* o0 = &out[((size_t)(n * CTX + i0 + g))     * D_MODEL + h * HD];
    float* o1 = &out[((size_t)(n * CTX + i0 + g + 8)) * D_MODEL + h * HD];
#pragma unroll
    for (int nt = 0; nt < 8; nt++) {
        *(float2*)&o0[nt * 8 + 2 * tig] = make_float2(oacc[nt][0] * inv0, oacc[nt][1] * inv0);
        *(float2*)&o1[nt * 8 + 2 * tig] = make_float2(oacc[nt][2] * inv1, oacc[nt][3] * inv1);
    }
}

extern "C" void kernel_launch(void* const* d_in, const int* in_sizes, int n_in,
                              void* d_out, int out_size) {
    const float* x = (const float*)d_in[0];
    const float* W = (const float*)d_in[1];
    const float* b = (const float*)d_in[2];
    float* out = (float*)d_out;

    const int n4x = TOK * D_MODEL / 4;
    const int n4w = EDIM * D_MODEL / 4;
    presplit_k<<<(n4x + 255) / 256, 256>>>(x, 0, n4x);
    presplit_k<<<(n4w + 255) / 256, 256>>>(W, 1, n4w);

    cudaFuncSetAttribute(qkv_gemm_bf, cudaFuncAttributeMaxDynamicSharedMemorySize,
                         GEMM_SMEM_BYTES);
    dim3 g1(EDIM / 128, TOK / 128);   // 24 x 64
    qkv_gemm_bf<<<g1, 256, GEMM_SMEM_BYTES>>>(b);

    cudaFuncSetAttribute(attn_tc, cudaFuncAttributeMaxDynamicSharedMemorySize,
                         ATTN_SMEM_BYTES);
    dim3 g2(CTX / 128, NHEADS, NB);   // 16 x 16 x 4
    attn_tc<<<g2, 256, ATTN_SMEM_BYTES>>>(out);
}

// round 8
// speedup vs baseline: 3.4536x; 1.0007x over previous
#include <cuda_runtime.h>
#include <cuda_bf16.h>
#include <math.h>
#include <stdint.h>

#define D_MODEL 1024
#define NHEADS  16
#define HD      64
#define NB      4
#define CTX     2048
#define EDIM    (3 * D_MODEL)
#define TOK     (NB * CTX)

__device__ float g_z[(size_t)TOK * EDIM];
// pre-split bf16 hi/lo copies of x and W
__device__ __nv_bfloat16 g_xh[(size_t)TOK * D_MODEL];
__device__ __nv_bfloat16 g_xl[(size_t)TOK * D_MODEL];
__device__ __nv_bfloat16 g_wh[(size_t)EDIM * D_MODEL];
__device__ __nv_bfloat16 g_wl[(size_t)EDIM * D_MODEL];

__device__ __forceinline__ uint32_t smem_u32(const void* p) {
    return (uint32_t)__cvta_generic_to_shared(p);
}

#define CP_ASYNC16(dst, src) \
    asm volatile("cp.async.ca.shared.global [%0], [%1], 16;\n" :: "r"(dst), "l"(src))
#define CP_COMMIT()  asm volatile("cp.async.commit_group;\n" ::: "memory")
#define CP_WAIT1()   asm volatile("cp.async.wait_group 1;\n" ::: "memory")
#define CP_WAIT0()   asm volatile("cp.async.wait_group 0;\n" ::: "memory")

__device__ __forceinline__ void mma_tf32(float* c, const uint32_t* a, const uint32_t* b) {
    asm volatile(
        "mma.sync.aligned.m16n8k8.row.col.f32.tf32.tf32.f32 "
        "{%0,%1,%2,%3}, {%4,%5,%6,%7}, {%8,%9}, {%0,%1,%2,%3};"
        : "+f"(c[0]), "+f"(c[1]), "+f"(c[2]), "+f"(c[3])
        : "r"(a[0]), "r"(a[1]), "r"(a[2]), "r"(a[3]), "r"(b[0]), "r"(b[1]));
}

__device__ __forceinline__ void mma_bf16(float* c, const uint32_t* a, const uint32_t* b) {
    asm volatile(
        "mma.sync.aligned.m16n8k16.row.col.f32.bf16.bf16.f32 "
        "{%0,%1,%2,%3}, {%4,%5,%6,%7}, {%8,%9}, {%0,%1,%2,%3};"
        : "+f"(c[0]), "+f"(c[1]), "+f"(c[2]), "+f"(c[3])
        : "r"(a[0]), "r"(a[1]), "r"(a[2]), "r"(a[3]), "r"(b[0]), "r"(b[1]));
}

__device__ __forceinline__ void split_bf16x2(float a, float b, uint32_t& hi, uint32_t& lo) {
    __nv_bfloat162 h = __floats2bfloat162_rn(a, b);
    float ra = a - __low2float(h);
    float rb = b - __high2float(h);
    __nv_bfloat162 l = __floats2bfloat162_rn(ra, rb);
    hi = *reinterpret_cast<uint32_t*>(&h);
    lo = *reinterpret_cast<uint32_t*>(&l);
}

__device__ __forceinline__ uint32_t cvt_rna_tf32(float v) {
    uint32_t u;
    asm("cvt.rna.tf32.f32 %0, %1;" : "=r"(u) : "f"(v));
    return u;
}

// ---------------------------------------------------------------------------
// Kernel 0: split fp32 -> bf16 hi + bf16 lo (residual). sel: 0 = x, 1 = W.
// ---------------------------------------------------------------------------
__global__ __launch_bounds__(256) void presplit_k(const float* __restrict__ src,
                                                  int sel, int n4) {
    int i = blockIdx.x * 256 + threadIdx.x;
    if (i >= n4) return;
    float4 v = ((const float4*)src)[i];
    __nv_bfloat162 h0 = __floats2bfloat162_rn(v.x, v.y);
    __nv_bfloat162 l0 = __floats2bfloat162_rn(v.x - __low2float(h0), v.y - __high2float(h0));
    __nv_bfloat162 h1 = __floats2bfloat162_rn(v.z, v.w);
    __nv_bfloat162 l1 = __floats2bfloat162_rn(v.z - __low2float(h1), v.w - __high2float(h1));
    uint2 H, L;
    H.x = *reinterpret_cast<uint32_t*>(&h0);
    H.y = *reinterpret_cast<uint32_t*>(&h1);
    L.x = *reinterpret_cast<uint32_t*>(&l0);
    L.y = *reinterpret_cast<uint32_t*>(&l1);
    if (sel == 0) {
        ((uint2*)g_xh)[i] = H;
        ((uint2*)g_xl)[i] = L;
    } else {
        ((uint2*)g_wh)[i] = H;
        ((uint2*)g_wl)[i] = L;
    }
}

// ---------------------------------------------------------------------------
// Kernel 1: z = x @ W^T + b, bf16 3-term mma.sync GEMM on PRE-SPLIT operands.
// Inner loop: pure LDS.32 + mma (no conversion math).
// 128x128 tile, 8 warps (warp tile 64x32), K chunks of 32, double buffered.
// smem rows: 32 bf16 data + 8 pad = 40 bf16 = 20 u32 -> conflict-free frags.
// ---------------------------------------------------------------------------
#define GROW32  20                 // uint32 per smem row
#define GTILEB  (128 * GROW32 * 4) // 10240 bytes per tile
#define GBUFB   (4 * GTILEB)       // Ah, Al, Bh, Bl
#define GEMM_SMEM_BYTES (2 * GBUFB)
#define G_NCH   (D_MODEL / 32)     // 32 chunks

__global__ __launch_bounds__(256, 2) void qkv_gemm_bf(const float* __restrict__ bias) {
    extern __shared__ char smg[];
    const uint32_t sb = smem_u32(smg);

    const int tid  = threadIdx.x;
    const int lane = tid & 31;
    const int warp = tid >> 5;
    const int g    = lane >> 2;
    const int tig  = lane & 3;
    const int wm   = warp >> 2;
    const int wn   = warp & 3;
    const int t0   = blockIdx.y * 128;
    const int e0   = blockIdx.x * 128;

    float acc[4][4][4];
#pragma unroll
    for (int a = 0; a < 4; a++)
#pragma unroll
        for (int bq = 0; bq < 4; bq++)
#pragma unroll
            for (int c = 0; c < 4; c++) acc[a][bq][c] = 0.f;

    auto load_chunk = [&](int ch, int buf) {
        const __nv_bfloat16* s0 = g_xh + (size_t)t0 * D_MODEL + ch * 32;
        const __nv_bfloat16* s1 = g_xl + (size_t)t0 * D_MODEL + ch * 32;
        const __nv_bfloat16* s2 = g_wh + (size_t)e0 * D_MODEL + ch * 32;
        const __nv_bfloat16* s3 = g_wl + (size_t)e0 * D_MODEL + ch * 32;
        const __nv_bfloat16* srcs[4] = {s0, s1, s2, s3};
        const uint32_t bb = sb + buf * GBUFB;
#pragma unroll
        for (int u = 0; u < 8; u++) {
            const int idx = tid + u * 256;       // 0..2047
            const int t   = idx >> 9;            // tile 0..3
            const int r   = idx & 511;
            const int row = r >> 2;              // 0..127
            const int seg = r & 3;               // 16B segment
            CP_ASYNC16(bb + t * GTILEB + row * 80 + seg * 16,
                       srcs[t] + (size_t)row * D_MODEL + seg * 8);
        }
    };

    load_chunk(0, 0);
    CP_COMMIT();

    for (int it = 0; it < G_NCH; it++) {
        const int buf = it & 1;
        if (it + 1 < G_NCH) {
            load_chunk(it + 1, buf ^ 1);
            CP_COMMIT();
            CP_WAIT1();
        } else {
            CP_WAIT0();
        }
        __syncthreads();

        const uint32_t* Ah = (const uint32_t*)(smg + buf * GBUFB);
        const uint32_t* Al = Ah + GTILEB / 4;
        const uint32_t* Bh = Al + GTILEB / 4;
        const uint32_t* Bl = Bh + GTILEB / 4;

#pragma unroll
        for (int ks = 0; ks < 2; ks++) {
            const int kb = ks * 8 + tig;
            uint32_t ah[4][4], al[4][4];
#pragma unroll
            for (int mi = 0; mi < 4; mi++) {
                const int m0 = (wm * 64 + mi * 16 + g) * GROW32;
                ah[mi][0] = Ah[m0 + kb];
                ah[mi][1] = Ah[m0 + 8 * GROW32 + kb];
                ah[mi][2] = Ah[m0 + kb + 4];
                ah[mi][3] = Ah[m0 + 8 * GROW32 + kb + 4];
                al[mi][0] = Al[m0 + kb];
                al[mi][1] = Al[m0 + 8 * GROW32 + kb];
                al[mi][2] = Al[m0 + kb + 4];
                al[mi][3] = Al[m0 + 8 * GROW32 + kb + 4];
            }
#pragma unroll
            for (int ni = 0; ni < 4; ni++) {
                const int n0 = (wn * 32 + ni * 8 + g) * GROW32;
                uint32_t bh[2], bl[2];
                bh[0] = Bh[n0 + kb];
                bh[1] = Bh[n0 + kb + 4];
                bl[0] = Bl[n0 + kb];
                bl[1] = Bl[n0 + kb + 4];
#pragma unroll
                for (int mi = 0; mi < 4; mi++) {
                    mma_bf16(acc[mi][ni], ah[mi], bh);
                    mma_bf16(acc[mi][ni], al[mi], bh);
                    mma_bf16(acc[mi][ni], ah[mi], bl);
                }
            }
        }
        __syncthreads();
    }

#pragma unroll
    for (int mi = 0; mi < 4; mi++) {
        const int m = t0 + wm * 64 + mi * 16 + g;
#pragma unroll
        for (int ni = 0; ni < 4; ni++) {
            const int e = e0 + wn * 32 + ni * 8 + 2 * tig;
            const float b0 = bias[e], b1 = bias[e + 1];
            float2 r0, r1;
            r0.x = acc[mi][ni][0] + b0;
            r0.y = acc[mi][ni][1] + b1;
            r1.x = acc[mi][ni][2] + b0;
            r1.y = acc[mi][ni][3] + b1;
            *(float2*)&g_z[(size_t)m * EDIM + e]       = r0;
            *(float2*)&g_z[(size_t)(m + 8) * EDIM + e] = r1;
        }
    }
}

// ---------------------------------------------------------------------------
// Kernel 2: tensor-core flash attention. NEW: cooperative V pre-convert to
// bf16 hi/lo TRANSPOSED smem (one pass per tile per CTA, amortized over all
// 8 warps); PV B-fragments become two LDS.32 each.
// ---------------------------------------------------------------------------
#define PAD   76
#define KVF   (64 * PAD)
#define OFF_K0 0
#define OFF_V0 (KVF)
#define OFF_K1 (2 * KVF)
#define OFF_V1 (3 * KVF)
#define VTROW  41                   // uint32 per transposed col (32 + 9 pad)
#define VTSZ   (64 * VTROW)         // u32 per V-transposed array
#define OFF_VT (4 * KVF)            // u32 index base: [Vth0][Vtl0][Vth1][Vtl1]
#define ATTN_SMEM_BYTES ((4 * KVF + 4 * VTSZ) * 4)

__global__ __launch_bounds__(256) void attn_tc(float* __restrict__ out) {
    extern __shared__ float sm[];
    uint32_t* smu = (uint32_t*)sm;

    const int qb   = (int)gridDim.x - 1 - (int)blockIdx.x;
    const int h    = blockIdx.y;
    const int n    = blockIdx.z;
    const int tid  = threadIdx.x;
    const int lane = tid & 31;
    const int warp = tid >> 5;
    const int g    = lane >> 2;
    const int tig  = lane & 3;

    const int i0 = qb * 128 + warp * 16;
    const float scale = 1.0f / 32.0f;

    uint32_t qa[8][4];
    {
        const float* zq = &g_z[((size_t)(n * CTX)) * EDIM + D_MODEL + h * HD];
        const float* r0 = &zq[(size_t)(i0 + g) * EDIM];
        const float* r1 = &zq[(size_t)(i0 + g + 8) * EDIM];
#pragma unroll
        for (int ks = 0; ks < 8; ks++) {
            qa[ks][0] = cvt_rna_tf32(r0[ks * 8 + tig] * scale);
            qa[ks][1] = cvt_rna_tf32(r1[ks * 8 + tig] * scale);
            qa[ks][2] = cvt_rna_tf32(r0[ks * 8 + tig + 4] * scale);
            qa[ks][3] = cvt_rna_tf32(r1[ks * 8 + tig + 4] * scale);
        }
    }

    float oacc[8][4];
#pragma unroll
    for (int nt = 0; nt < 8; nt++)
#pragma unroll
        for (int c = 0; c < 4; c++) oacc[nt][c] = 0.f;
    float m0 = -1e30f, m1 = -1e30f, l0 = 0.f, l1 = 0.f;

    const int ntiles   = qb * 2 + 2;
    const int my_tiles = qb * 2 + 1 + (warp >> 2);

    auto load_tile = [&](int jt, int buf) {
        const float* zk = &g_z[((size_t)(n * CTX + jt * 64)) * EDIM + h * HD];
        const float* zv = zk + 2 * D_MODEL;
        float* Kd = &sm[buf ? OFF_K1 : OFF_K0];
        float* Vd = &sm[buf ? OFF_V1 : OFF_V0];
#pragma unroll
        for (int u = 0; u < 4; u++) {
            const int idx = tid + u * 256;
            const int row = idx >> 4;
            const int c4  = (idx & 15) * 4;
            CP_ASYNC16(smem_u32(&Kd[row * PAD + c4]), &zk[(size_t)row * EDIM + c4]);
            CP_ASYNC16(smem_u32(&Vd[row * PAD + c4]), &zv[(size_t)row * EDIM + c4]);
        }
    };

    load_tile(0, 0);
    CP_COMMIT();

    for (int jt = 0; jt < ntiles; jt++) {
        const int buf = jt & 1;
        if (jt + 1 < ntiles) {
            load_tile(jt + 1, buf ^ 1);
            CP_COMMIT();
            CP_WAIT1();
        } else {
            CP_WAIT0();
        }
        __syncthreads();

        const float* Ks = &sm[buf ? OFF_K1 : OFF_K0];
        const float* Vs = &sm[buf ? OFF_V1 : OFF_V0];
        uint32_t* Vth = smu + OFF_VT + buf * 2 * VTSZ;
        uint32_t* Vtl = Vth + VTSZ;

        // ---- cooperative V convert: fp32 [k][col] -> bf16 hi/lo [col][kpair] ----
#pragma unroll
        for (int u = 0; u < 8; u++) {
            const int idx = tid + u * 256;     // 0..2047
            const int col = idx & 63;
            const int kp  = idx >> 6;          // k-pair 0..31
            uint32_t hi, lo;
            split_bf16x2(Vs[(2 * kp) * PAD + col], Vs[(2 * kp + 1) * PAD + col], hi, lo);
            Vth[col * VTROW + kp] = hi;
            Vtl[col * VTROW + kp] = lo;
        }
        __syncthreads();

        if (jt < my_tiles) {
            // ---- S = Q K^T ----
            float sc[8][4];
#pragma unroll
            for (int nt = 0; nt < 8; nt++) {
                float a4[4] = {0.f, 0.f, 0.f, 0.f};
#pragma unroll
                for (int ks = 0; ks < 8; ks++) {
                    uint32_t b[2];
                    b[0] = __float_as_uint(Ks[(nt * 8 + g) * PAD + ks * 8 + tig]) & 0xffffe000u;
                    b[1] = __float_as_uint(Ks[(nt * 8 + g) * PAD + ks * 8 + tig + 4]) & 0xffffe000u;
                    mma_tf32(a4, qa[ks], b);
                }
                sc[nt][0] = a4[0]; sc[nt][1] = a4[1]; sc[nt][2] = a4[2]; sc[nt][3] = a4[3];
            }

            if (jt == my_tiles - 1) {
                const int r0 = i0 + g, r1 = i0 + g + 8;
#pragma unroll
                for (int nt = 0; nt < 8; nt++) {
                    const int j = jt * 64 + nt * 8 + 2 * tig;
                    if (j     > r0) sc[nt][0] = -INFINITY;
                    if (j + 1 > r0) sc[nt][1] = -INFINITY;
                    if (j     > r1) sc[nt][2] = -INFINITY;
                    if (j + 1 > r1) sc[nt][3] = -INFINITY;
                }
            }

            // ---- online softmax ----
            float mx0 = -INFINITY, mx1 = -INFINITY;
#pragma unroll
            for (int nt = 0; nt < 8; nt++) {
                mx0 = fmaxf(mx0, fmaxf(sc[nt][0], sc[nt][1]));
                mx1 = fmaxf(mx1, fmaxf(sc[nt][2], sc[nt][3]));
            }
            mx0 = fmaxf(mx0, __shfl_xor_sync(0xffffffffu, mx0, 1));
            mx0 = fmaxf(mx0, __shfl_xor_sync(0xffffffffu, mx0, 2));
            mx1 = fmaxf(mx1, __shfl_xor_sync(0xffffffffu, mx1, 1));
            mx1 = fmaxf(mx1, __shfl_xor_sync(0xffffffffu, mx1, 2));

            const float mn0 = fmaxf(m0, mx0);
            const float mn1 = fmaxf(m1, mx1);
            const float c0 = __expf(m0 - mn0);
            const float c1 = __expf(m1 - mn1);
            m0 = mn0; m1 = mn1;

            float rs0 = 0.f, rs1 = 0.f;
#pragma unroll
            for (int nt = 0; nt < 8; nt++) {
                sc[nt][0] = __expf(sc[nt][0] - mn0);
                sc[nt][1] = __expf(sc[nt][1] - mn0);
                sc[nt][2] = __expf(sc[nt][2] - mn1);
                sc[nt][3] = __expf(sc[nt][3] - mn1);
                rs0 += sc[nt][0] + sc[nt][1];
                rs1 += sc[nt][2] + sc[nt][3];
            }
            rs0 += __shfl_xor_sync(0xffffffffu, rs0, 1);
            rs0 += __shfl_xor_sync(0xffffffffu, rs0, 2);
            rs1 += __shfl_xor_sync(0xffffffffu, rs1, 1);
            rs1 += __shfl_xor_sync(0xffffffffu, rs1, 2);
            l0 = l0 * c0 + rs0;
            l1 = l1 * c1 + rs1;

#pragma unroll
            for (int nt = 0; nt < 8; nt++) {
                oacc[nt][0] *= c0; oacc[nt][1] *= c0;
                oacc[nt][2] *= c1; oacc[nt][3] *= c1;
            }

            // ---- O += P V  (bf16x2 3-mma; V frags via 2x LDS.32) ----
#pragma unroll
            for (int ks = 0; ks < 4; ks++) {
                uint32_t ah[4], al[4];
                split_bf16x2(sc[2 * ks][0],     sc[2 * ks][1],     ah[0], al[0]);
                split_bf16x2(sc[2 * ks][2],     sc[2 * ks][3],     ah[1], al[1]);
                split_bf16x2(sc[2 * ks + 1][0], sc[2 * ks + 1][1], ah[2], al[2]);
                split_bf16x2(sc[2 * ks + 1][2], sc[2 * ks + 1][3], ah[3], al[3]);
#pragma unroll
                for (int nt = 0; nt < 8; nt++) {
                    const uint32_t* vh = &Vth[(nt * 8 + g) * VTROW + 8 * ks + tig];
                    const uint32_t* vl = &Vtl[(nt * 8 + g) * VTROW + 8 * ks + tig];
                    uint32_t bh[2] = {vh[0], vh[4]};
                    uint32_t bl[2] = {vl[0], vl[4]};
                    mma_bf16(oacc[nt], ah, bh);
                    mma_bf16(oacc[nt], al, bh);
                    mma_bf16(oacc[nt], ah, bl);
                }
            }
        }

        __syncthreads();
    }

    const float inv0 = 1.f / l0;
    const float inv1 = 1.f / l1;
    float* o0 = &out[((size_t)(n * CTX + i0 + g))     * D_MODEL + h * HD];
    float* o1 = &out[((size_t)(n * CTX + i0 + g + 8)) * D_MODEL + h * HD];
#pragma unroll
    for (int nt = 0; nt < 8; nt++) {
        *(float2*)&o0[nt * 8 + 2 * tig] = make_float2(oacc[nt][0] * inv0, oacc[nt][1] * inv0);
        *(float2*)&o1[nt * 8 + 2 * tig] = make_float2(oacc[nt][2] * inv1, oacc[nt][3] * inv1);
    }
}

extern "C" void kernel_launch(void* const* d_in, const int* in_sizes, int n_in,
                              void* d_out, int out_size) {
    const float* x = (const float*)d_in[0];
    const float* W = (const float*)d_in[1];
    const float* b = (const float*)d_in[2];
    float* out = (float*)d_out;

    const int n4x = TOK * D_MODEL / 4;
    const int n4w = EDIM * D_MODEL / 4;
    presplit_k<<<(n4x + 255) / 256, 256>>>(x, 0, n4x);
    presplit_k<<<(n4w + 255) / 256, 256>>>(W, 1, n4w);

    cudaFuncSetAttribute(qkv_gemm_bf, cudaFuncAttributeMaxDynamicSharedMemorySize,
                         GEMM_SMEM_BYTES);
    dim3 g1(EDIM / 128, TOK / 128);   // 24 x 64
    qkv_gemm_bf<<<g1, 256, GEMM_SMEM_BYTES>>>(b);

    cudaFuncSetAttribute(attn_tc, cudaFuncAttributeMaxDynamicSharedMemorySize,
                         ATTN_SMEM_BYTES);
    dim3 g2(CTX / 128, NHEADS, NB);   // 16 x 16 x 4
    attn_tc<<<g2, 256, ATTN_SMEM_BYTES>>>(out);
}

// round 9
// speedup vs baseline: 3.7157x; 1.0759x over previous
#include <cuda_runtime.h>
#include <cuda_bf16.h>
#include <math.h>
#include <stdint.h>

#define D_MODEL 1024
#define NHEADS  16
#define HD      64
#define NB      4
#define CTX     2048
#define EDIM    (3 * D_MODEL)
#define TOK     (NB * CTX)

__device__ float g_z[(size_t)TOK * EDIM];
__device__ __nv_bfloat16 g_xh[(size_t)TOK * D_MODEL];
__device__ __nv_bfloat16 g_xl[(size_t)TOK * D_MODEL];
__device__ __nv_bfloat16 g_wh[(size_t)EDIM * D_MODEL];
__device__ __nv_bfloat16 g_wl[(size_t)EDIM * D_MODEL];

__device__ __forceinline__ uint32_t smem_u32(const void* p) {
    return (uint32_t)__cvta_generic_to_shared(p);
}

#define CP_ASYNC16(dst, src) \
    asm volatile("cp.async.ca.shared.global [%0], [%1], 16;\n" :: "r"(dst), "l"(src))
#define CP_COMMIT()  asm volatile("cp.async.commit_group;\n" ::: "memory")
#define CP_WAIT1()   asm volatile("cp.async.wait_group 1;\n" ::: "memory")
#define CP_WAIT0()   asm volatile("cp.async.wait_group 0;\n" ::: "memory")

__device__ __forceinline__ void mma_tf32(float* c, const uint32_t* a, const uint32_t* b) {
    asm volatile(
        "mma.sync.aligned.m16n8k8.row.col.f32.tf32.tf32.f32 "
        "{%0,%1,%2,%3}, {%4,%5,%6,%7}, {%8,%9}, {%0,%1,%2,%3};"
        : "+f"(c[0]), "+f"(c[1]), "+f"(c[2]), "+f"(c[3])
        : "r"(a[0]), "r"(a[1]), "r"(a[2]), "r"(a[3]), "r"(b[0]), "r"(b[1]));
}

__device__ __forceinline__ void mma_bf16(float* c, const uint32_t* a, const uint32_t* b) {
    asm volatile(
        "mma.sync.aligned.m16n8k16.row.col.f32.bf16.bf16.f32 "
        "{%0,%1,%2,%3}, {%4,%5,%6,%7}, {%8,%9}, {%0,%1,%2,%3};"
        : "+f"(c[0]), "+f"(c[1]), "+f"(c[2]), "+f"(c[3])
        : "r"(a[0]), "r"(a[1]), "r"(a[2]), "r"(a[3]), "r"(b[0]), "r"(b[1]));
}

__device__ __forceinline__ void split_bf16x2(float a, float b, uint32_t& hi, uint32_t& lo) {
    __nv_bfloat162 h = __floats2bfloat162_rn(a, b);
    float ra = a - __low2float(h);
    float rb = b - __high2float(h);
    __nv_bfloat162 l = __floats2bfloat162_rn(ra, rb);
    hi = *reinterpret_cast<uint32_t*>(&h);
    lo = *reinterpret_cast<uint32_t*>(&l);
}

__device__ __forceinline__ uint32_t cvt_rna_tf32(float v) {
    uint32_t u;
    asm("cvt.rna.tf32.f32 %0, %1;" : "=r"(u) : "f"(v));
    return u;
}

// ---------------------------------------------------------------------------
// Kernel 0: split fp32 -> bf16 hi + bf16 lo (residual). sel: 0 = x, 1 = W.
// ---------------------------------------------------------------------------
__global__ __launch_bounds__(256) void presplit_k(const float* __restrict__ src,
                                                  int sel, int n4) {
    int i = blockIdx.x * 256 + threadIdx.x;
    if (i >= n4) return;
    float4 v = ((const float4*)src)[i];
    __nv_bfloat162 h0 = __floats2bfloat162_rn(v.x, v.y);
    __nv_bfloat162 l0 = __floats2bfloat162_rn(v.x - __low2float(h0), v.y - __high2float(h0));
    __nv_bfloat162 h1 = __floats2bfloat162_rn(v.z, v.w);
    __nv_bfloat162 l1 = __floats2bfloat162_rn(v.z - __low2float(h1), v.w - __high2float(h1));
    uint2 H, L;
    H.x = *reinterpret_cast<uint32_t*>(&h0);
    H.y = *reinterpret_cast<uint32_t*>(&h1);
    L.x = *reinterpret_cast<uint32_t*>(&l0);
    L.y = *reinterpret_cast<uint32_t*>(&l1);
    if (sel == 0) {
        ((uint2*)g_xh)[i] = H;
        ((uint2*)g_xl)[i] = L;
    } else {
        ((uint2*)g_wh)[i] = H;
        ((uint2*)g_wl)[i] = L;
    }
}

// ---------------------------------------------------------------------------
// Kernel 1: bf16 3-term mma.sync GEMM on pre-split operands (unchanged, R8).
// ---------------------------------------------------------------------------
#define GROW32  20
#define GTILEB  (128 * GROW32 * 4)
#define GBUFB   (4 * GTILEB)
#define GEMM_SMEM_BYTES (2 * GBUFB)
#define G_NCH   (D_MODEL / 32)

__global__ __launch_bounds__(256, 2) void qkv_gemm_bf(const float* __restrict__ bias) {
    extern __shared__ char smg[];
    const uint32_t sb = smem_u32(smg);

    const int tid  = threadIdx.x;
    const int lane = tid & 31;
    const int warp = tid >> 5;
    const int g    = lane >> 2;
    const int tig  = lane & 3;
    const int wm   = warp >> 2;
    const int wn   = warp & 3;
    const int t0   = blockIdx.y * 128;
    const int e0   = blockIdx.x * 128;

    float acc[4][4][4];
#pragma unroll
    for (int a = 0; a < 4; a++)
#pragma unroll
        for (int bq = 0; bq < 4; bq++)
#pragma unroll
            for (int c = 0; c < 4; c++) acc[a][bq][c] = 0.f;

    auto load_chunk = [&](int ch, int buf) {
        const __nv_bfloat16* s0 = g_xh + (size_t)t0 * D_MODEL + ch * 32;
        const __nv_bfloat16* s1 = g_xl + (size_t)t0 * D_MODEL + ch * 32;
        const __nv_bfloat16* s2 = g_wh + (size_t)e0 * D_MODEL + ch * 32;
        const __nv_bfloat16* s3 = g_wl + (size_t)e0 * D_MODEL + ch * 32;
        const __nv_bfloat16* srcs[4] = {s0, s1, s2, s3};
        const uint32_t bb = sb + buf * GBUFB;
#pragma unroll
        for (int u = 0; u < 8; u++) {
            const int idx = tid + u * 256;
            const int t   = idx >> 9;
            const int r   = idx & 511;
            const int row = r >> 2;
            const int seg = r & 3;
            CP_ASYNC16(bb + t * GTILEB + row * 80 + seg * 16,
                       srcs[t] + (size_t)row * D_MODEL + seg * 8);
        }
    };

    load_chunk(0, 0);
    CP_COMMIT();

    for (int it = 0; it < G_NCH; it++) {
        const int buf = it & 1;
        if (it + 1 < G_NCH) {
            load_chunk(it + 1, buf ^ 1);
            CP_COMMIT();
            CP_WAIT1();
        } else {
            CP_WAIT0();
        }
        __syncthreads();

        const uint32_t* Ah = (const uint32_t*)(smg + buf * GBUFB);
        const uint32_t* Al = Ah + GTILEB / 4;
        const uint32_t* Bh = Al + GTILEB / 4;
        const uint32_t* Bl = Bh + GTILEB / 4;

#pragma unroll
        for (int ks = 0; ks < 2; ks++) {
            const int kb = ks * 8 + tig;
            uint32_t ah[4][4], al[4][4];
#pragma unroll
            for (int mi = 0; mi < 4; mi++) {
                const int m0 = (wm * 64 + mi * 16 + g) * GROW32;
                ah[mi][0] = Ah[m0 + kb];
                ah[mi][1] = Ah[m0 + 8 * GROW32 + kb];
                ah[mi][2] = Ah[m0 + kb + 4];
                ah[mi][3] = Ah[m0 + 8 * GROW32 + kb + 4];
                al[mi][0] = Al[m0 + kb];
                al[mi][1] = Al[m0 + 8 * GROW32 + kb];
                al[mi][2] = Al[m0 + kb + 4];
                al[mi][3] = Al[m0 + 8 * GROW32 + kb + 4];
            }
#pragma unroll
            for (int ni = 0; ni < 4; ni++) {
                const int n0 = (wn * 32 + ni * 8 + g) * GROW32;
                uint32_t bh[2], bl[2];
                bh[0] = Bh[n0 + kb];
                bh[1] = Bh[n0 + kb + 4];
                bl[0] = Bl[n0 + kb];
                bl[1] = Bl[n0 + kb + 4];
#pragma unroll
                for (int mi = 0; mi < 4; mi++) {
                    mma_bf16(acc[mi][ni], ah[mi], bh);
                    mma_bf16(acc[mi][ni], al[mi], bh);
                    mma_bf16(acc[mi][ni], ah[mi], bl);
                }
            }
        }
        __syncthreads();
    }

#pragma unroll
    for (int mi = 0; mi < 4; mi++) {
        const int m = t0 + wm * 64 + mi * 16 + g;
#pragma unroll
        for (int ni = 0; ni < 4; ni++) {
            const int e = e0 + wn * 32 + ni * 8 + 2 * tig;
            const float b0 = bias[e], b1 = bias[e + 1];
            float2 r0, r1;
            r0.x = acc[mi][ni][0] + b0;
            r0.y = acc[mi][ni][1] + b1;
            r1.x = acc[mi][ni][2] + b0;
            r1.y = acc[mi][ni][3] + b1;
            *(float2*)&g_z[(size_t)m * EDIM + e]       = r0;
            *(float2*)&g_z[(size_t)(m + 8) * EDIM + e] = r1;
        }
    }
}

// ---------------------------------------------------------------------------
// Kernel 2: tensor-core flash attention, smem diet for 2 CTAs/SM.
// K: fp32, cp.async double-buffered (2 x 19 KB).
// V: converted straight from gmem -> transposed bf16 hi/lo smem, SINGLE buffer
//    (21 KB), rebuilt each tile between syncs. No fp32 V staging.
// ---------------------------------------------------------------------------
#define PAD   76
#define KVF   (64 * PAD)
#define OFF_K0 0
#define OFF_K1 (KVF)
#define VTROW  41
#define VTSZ   (64 * VTROW)
#define OFF_VT (2 * KVF)            // u32 index: [Vth][Vtl]
#define ATTN_SMEM_BYTES ((2 * KVF + 2 * VTSZ) * 4)

__global__ __launch_bounds__(256, 2) void attn_tc(float* __restrict__ out) {
    extern __shared__ float sm[];
    uint32_t* smu = (uint32_t*)sm;

    const int qb   = (int)gridDim.x - 1 - (int)blockIdx.x;
    const int h    = blockIdx.y;
    const int n    = blockIdx.z;
    const int tid  = threadIdx.x;
    const int lane = tid & 31;
    const int warp = tid >> 5;
    const int g    = lane >> 2;
    const int tig  = lane & 3;

    const int i0 = qb * 128 + warp * 16;
    const float scale = 1.0f / 32.0f;

    uint32_t qa[8][4];
    {
        const float* zq = &g_z[((size_t)(n * CTX)) * EDIM + D_MODEL + h * HD];
        const float* r0 = &zq[(size_t)(i0 + g) * EDIM];
        const float* r1 = &zq[(size_t)(i0 + g + 8) * EDIM];
#pragma unroll
        for (int ks = 0; ks < 8; ks++) {
            qa[ks][0] = cvt_rna_tf32(r0[ks * 8 + tig] * scale);
            qa[ks][1] = cvt_rna_tf32(r1[ks * 8 + tig] * scale);
            qa[ks][2] = cvt_rna_tf32(r0[ks * 8 + tig + 4] * scale);
            qa[ks][3] = cvt_rna_tf32(r1[ks * 8 + tig + 4] * scale);
        }
    }

    float oacc[8][4];
#pragma unroll
    for (int nt = 0; nt < 8; nt++)
#pragma unroll
        for (int c = 0; c < 4; c++) oacc[nt][c] = 0.f;
    float m0 = -1e30f, m1 = -1e30f, l0 = 0.f, l1 = 0.f;

    const int ntiles   = qb * 2 + 2;
    const int my_tiles = qb * 2 + 1 + (warp >> 2);

    uint32_t* Vth = smu + OFF_VT;
    uint32_t* Vtl = Vth + VTSZ;

    auto load_K = [&](int jt, int buf) {
        const float* zk = &g_z[((size_t)(n * CTX + jt * 64)) * EDIM + h * HD];
        float* Kd = &sm[buf ? OFF_K1 : OFF_K0];
#pragma unroll
        for (int u = 0; u < 4; u++) {
            const int idx = tid + u * 256;
            const int row = idx >> 4;
            const int c4  = (idx & 15) * 4;
            CP_ASYNC16(smem_u32(&Kd[row * PAD + c4]), &zk[(size_t)row * EDIM + c4]);
        }
    };

    load_K(0, 0);
    CP_COMMIT();

    for (int jt = 0; jt < ntiles; jt++) {
        const int buf = jt & 1;

        // sync[A]: previous tile's compute fully done -> VT and K[buf^1] free
        __syncthreads();

        if (jt + 1 < ntiles) {
            load_K(jt + 1, buf ^ 1);
            CP_COMMIT();
        }

        // ---- V convert: gmem fp32 -> transposed bf16 hi/lo (overlaps cp.async) ----
        {
            const float* zv = &g_z[((size_t)(n * CTX + jt * 64)) * EDIM + 2 * D_MODEL + h * HD];
#pragma unroll
            for (int u = 0; u < 8; u++) {
                const int idx = tid + u * 256;     // 0..2047
                const int col = idx & 63;
                const int kp  = idx >> 6;          // k-pair 0..31
                const float v0 = zv[(size_t)(2 * kp) * EDIM + col];
                const float v1 = zv[(size_t)(2 * kp + 1) * EDIM + col];
                uint32_t hi, lo;
                split_bf16x2(v0, v1, hi, lo);
                Vth[col * VTROW + kp] = hi;
                Vtl[col * VTROW + kp] = lo;
            }
        }

        if (jt + 1 < ntiles) CP_WAIT1(); else CP_WAIT0();
        __syncthreads();   // sync[B]: K[buf] + VT ready for all warps

        if (jt < my_tiles) {
            const float* Ks = &sm[buf ? OFF_K1 : OFF_K0];

            // ---- S = Q K^T ----
            float sc[8][4];
#pragma unroll
            for (int nt = 0; nt < 8; nt++) {
                float a4[4] = {0.f, 0.f, 0.f, 0.f};
#pragma unroll
                for (int ks = 0; ks < 8; ks++) {
                    uint32_t b[2];
                    b[0] = __float_as_uint(Ks[(nt * 8 + g) * PAD + ks * 8 + tig]) & 0xffffe000u;
                    b[1] = __float_as_uint(Ks[(nt * 8 + g) * PAD + ks * 8 + tig + 4]) & 0xffffe000u;
                    mma_tf32(a4, qa[ks], b);
                }
                sc[nt][0] = a4[0]; sc[nt][1] = a4[1]; sc[nt][2] = a4[2]; sc[nt][3] = a4[3];
            }

            if (jt == my_tiles - 1) {
                const int r0 = i0 + g, r1 = i0 + g + 8;
#pragma unroll
                for (int nt = 0; nt < 8; nt++) {
                    const int j = jt * 64 + nt * 8 + 2 * tig;
                    if (j     > r0) sc[nt][0] = -INFINITY;
                    if (j + 1 > r0) sc[nt][1] = -INFINITY;
                    if (j     > r1) sc[nt][2] = -INFINITY;
                    if (j + 1 > r1) sc[nt][3] = -INFINITY;
                }
            }

            // ---- online softmax ----
            float mx0 = -INFINITY, mx1 = -INFINITY;
#pragma unroll
            for (int nt = 0; nt < 8; nt++) {
                mx0 = fmaxf(mx0, fmaxf(sc[nt][0], sc[nt][1]));
                mx1 = fmaxf(mx1, fmaxf(sc[nt][2], sc[nt][3]));
            }
            mx0 = fmaxf(mx0, __shfl_xor_sync(0xffffffffu, mx0, 1));
            mx0 = fmaxf(mx0, __shfl_xor_sync(0xffffffffu, mx0, 2));
            mx1 = fmaxf(mx1, __shfl_xor_sync(0xffffffffu, mx1, 1));
            mx1 = fmaxf(mx1, __shfl_xor_sync(0xffffffffu, mx1, 2));

            const float mn0 = fmaxf(m0, mx0);
            const float mn1 = fmaxf(m1, mx1);
            const float c0 = __expf(m0 - mn0);
            const float c1 = __expf(m1 - mn1);
            m0 = mn0; m1 = mn1;

            float rs0 = 0.f, rs1 = 0.f;
#pragma unroll
            for (int nt = 0; nt < 8; nt++) {
                sc[nt][0] = __expf(sc[nt][0] - mn0);
                sc[nt][1] = __expf(sc[nt][1] - mn0);
                sc[nt][2] = __expf(sc[nt][2] - mn1);
                sc[nt][3] = __expf(sc[nt][3] - mn1);
                rs0 += sc[nt][0] + sc[nt][1];
                rs1 += sc[nt][2] + sc[nt][3];
            }
            rs0 += __shfl_xor_sync(0xffffffffu, rs0, 1);
            rs0 += __shfl_xor_sync(0xffffffffu, rs0, 2);
            rs1 += __shfl_xor_sync(0xffffffffu, rs1, 1);
            rs1 += __shfl_xor_sync(0xffffffffu, rs1, 2);
            l0 = l0 * c0 + rs0;
            l1 = l1 * c1 + rs1;

#pragma unroll
            for (int nt = 0; nt < 8; nt++) {
                oacc[nt][0] *= c0; oacc[nt][1] *= c0;
                oacc[nt][2] *= c1; oacc[nt][3] *= c1;
            }

            // ---- O += P V (bf16x2 3-mma; V frags via 2x LDS.32) ----
#pragma unroll
            for (int ks = 0; ks < 4; ks++) {
                uint32_t ah[4], al[4];
                split_bf16x2(sc[2 * ks][0],     sc[2 * ks][1],     ah[0], al[0]);
                split_bf16x2(sc[2 * ks][2],     sc[2 * ks][3],     ah[1], al[1]);
                split_bf16x2(sc[2 * ks + 1][0], sc[2 * ks + 1][1], ah[2], al[2]);
                split_bf16x2(sc[2 * ks + 1][2], sc[2 * ks + 1][3], ah[3], al[3]);
#pragma unroll
                for (int nt = 0; nt < 8; nt++) {
                    const uint32_t* vh = &Vth[(nt * 8 + g) * VTROW + 8 * ks + tig];
                    const uint32_t* vl = &Vtl[(nt * 8 + g) * VTROW + 8 * ks + tig];
                    uint32_t bh[2] = {vh[0], vh[4]};
                    uint32_t bl[2] = {vl[0], vl[4]};
                    mma_bf16(oacc[nt], ah, bh);
                    mma_bf16(oacc[nt], al, bh);
                    mma_bf16(oacc[nt], ah, bl);
                }
            }
        }
    }

    const float inv0 = 1.f / l0;
    const float inv1 = 1.f / l1;
    float* o0 = &out[((size_t)(n * CTX + i0 + g))     * D_MODEL + h * HD];
    float* o1 = &out[((size_t)(n * CTX + i0 + g + 8)) * D_MODEL + h * HD];
#pragma unroll
    for (int nt = 0; nt < 8; nt++) {
        *(float2*)&o0[nt * 8 + 2 * tig] = make_float2(oacc[nt][0] * inv0, oacc[nt][1] * inv0);
        *(float2*)&o1[nt * 8 + 2 * tig] = make_float2(oacc[nt][2] * inv1, oacc[nt][3] * inv1);
    }
}

extern "C" void kernel_launch(void* const* d_in, const int* in_sizes, int n_in,
                              void* d_out, int out_size) {
    const float* x = (const float*)d_in[0];
    const float* W = (const float*)d_in[1];
    const float* b = (const float*)d_in[2];
    float* out = (float*)d_out;

    const int n4x = TOK * D_MODEL / 4;
    const int n4w = EDIM * D_MODEL / 4;
    presplit_k<<<(n4x + 255) / 256, 256>>>(x, 0, n4x);
    presplit_k<<<(n4w + 255) / 256, 256>>>(W, 1, n4w);

    cudaFuncSetAttribute(qkv_gemm_bf, cudaFuncAttributeMaxDynamicSharedMemorySize,
                         GEMM_SMEM_BYTES);
    dim3 g1(EDIM / 128, TOK / 128);
    qkv_gemm_bf<<<g1, 256, GEMM_SMEM_BYTES>>>(b);

    cudaFuncSetAttribute(attn_tc, cudaFuncAttributeMaxDynamicSharedMemorySize,
                         ATTN_SMEM_BYTES);
    dim3 g2(CTX / 128, NHEADS, NB);
    attn_tc<<<g2, 256, ATTN_SMEM_BYTES>>>(out);
}

// round 10
// speedup vs baseline: 3.7579x; 1.0114x over previous
#include <cuda_runtime.h>
#include <cuda_bf16.h>
#include <math.h>
#include <stdint.h>

#define D_MODEL 1024
#define NHEADS  16
#define HD      64
#define NB      4
#define CTX     2048
#define EDIM    (3 * D_MODEL)
#define TOK     (NB * CTX)

__device__ float g_z[(size_t)TOK * EDIM];
__device__ __nv_bfloat16 g_xh[(size_t)TOK * D_MODEL];
__device__ __nv_bfloat16 g_xl[(size_t)TOK * D_MODEL];
__device__ __nv_bfloat16 g_wh[(size_t)EDIM * D_MODEL];
__device__ __nv_bfloat16 g_wl[(size_t)EDIM * D_MODEL];
// V third of z, transposed: [e' (1024)][token], bf16 hi / lo
__device__ __nv_bfloat16 g_vth[(size_t)D_MODEL * TOK];
__device__ __nv_bfloat16 g_vtl[(size_t)D_MODEL * TOK];

__device__ __forceinline__ uint32_t smem_u32(const void* p) {
    return (uint32_t)__cvta_generic_to_shared(p);
}

#define CP_ASYNC16(dst, src) \
    asm volatile("cp.async.ca.shared.global [%0], [%1], 16;\n" :: "r"(dst), "l"(src))
#define CP_COMMIT()  asm volatile("cp.async.commit_group;\n" ::: "memory")
#define CP_WAIT1()   asm volatile("cp.async.wait_group 1;\n" ::: "memory")
#define CP_WAIT0()   asm volatile("cp.async.wait_group 0;\n" ::: "memory")

__device__ __forceinline__ void mma_tf32(float* c, const uint32_t* a, const uint32_t* b) {
    asm volatile(
        "mma.sync.aligned.m16n8k8.row.col.f32.tf32.tf32.f32 "
        "{%0,%1,%2,%3}, {%4,%5,%6,%7}, {%8,%9}, {%0,%1,%2,%3};"
        : "+f"(c[0]), "+f"(c[1]), "+f"(c[2]), "+f"(c[3])
        : "r"(a[0]), "r"(a[1]), "r"(a[2]), "r"(a[3]), "r"(b[0]), "r"(b[1]));
}

__device__ __forceinline__ void mma_bf16(float* c, const uint32_t* a, const uint32_t* b) {
    asm volatile(
        "mma.sync.aligned.m16n8k16.row.col.f32.bf16.bf16.f32 "
        "{%0,%1,%2,%3}, {%4,%5,%6,%7}, {%8,%9}, {%0,%1,%2,%3};"
        : "+f"(c[0]), "+f"(c[1]), "+f"(c[2]), "+f"(c[3])
        : "r"(a[0]), "r"(a[1]), "r"(a[2]), "r"(a[3]), "r"(b[0]), "r"(b[1]));
}

__device__ __forceinline__ void split_bf16x2(float a, float b, uint32_t& hi, uint32_t& lo) {
    __nv_bfloat162 h = __floats2bfloat162_rn(a, b);
    float ra = a - __low2float(h);
    float rb = b - __high2float(h);
    __nv_bfloat162 l = __floats2bfloat162_rn(ra, rb);
    hi = *reinterpret_cast<uint32_t*>(&h);
    lo = *reinterpret_cast<uint32_t*>(&l);
}

__device__ __forceinline__ uint32_t cvt_rna_tf32(float v) {
    uint32_t u;
    asm("cvt.rna.tf32.f32 %0, %1;" : "=r"(u) : "f"(v));
    return u;
}

// ---------------------------------------------------------------------------
// Kernel 0: split fp32 -> bf16 hi + lo. sel: 0 = x, 1 = W.
// ---------------------------------------------------------------------------
__global__ __launch_bounds__(256) void presplit_k(const float* __restrict__ src,
                                                  int sel, int n4) {
    int i = blockIdx.x * 256 + threadIdx.x;
    if (i >= n4) return;
    float4 v = ((const float4*)src)[i];
    __nv_bfloat162 h0 = __floats2bfloat162_rn(v.x, v.y);
    __nv_bfloat162 l0 = __floats2bfloat162_rn(v.x - __low2float(h0), v.y - __high2float(h0));
    __nv_bfloat162 h1 = __floats2bfloat162_rn(v.z, v.w);
    __nv_bfloat162 l1 = __floats2bfloat162_rn(v.z - __low2float(h1), v.w - __high2float(h1));
    uint2 H, L;
    H.x = *reinterpret_cast<uint32_t*>(&h0);
    H.y = *reinterpret_cast<uint32_t*>(&h1);
    L.x = *reinterpret_cast<uint32_t*>(&l0);
    L.y = *reinterpret_cast<uint32_t*>(&l1);
    if (sel == 0) {
        ((uint2*)g_xh)[i] = H;
        ((uint2*)g_xl)[i] = L;
    } else {
        ((uint2*)g_wh)[i] = H;
        ((uint2*)g_wl)[i] = L;
    }
}

// ---------------------------------------------------------------------------
// Kernel 1: bf16 3-term mma.sync GEMM on pre-split operands (unchanged, R8).
// ---------------------------------------------------------------------------
#define GROW32  20
#define GTILEB  (128 * GROW32 * 4)
#define GBUFB   (4 * GTILEB)
#define GEMM_SMEM_BYTES (2 * GBUFB)
#define G_NCH   (D_MODEL / 32)

__global__ __launch_bounds__(256, 2) void qkv_gemm_bf(const float* __restrict__ bias) {
    extern __shared__ char smg[];
    const uint32_t sb = smem_u32(smg);

    const int tid  = threadIdx.x;
    const int lane = tid & 31;
    const int warp = tid >> 5;
    const int g    = lane >> 2;
    const int tig  = lane & 3;
    const int wm   = warp >> 2;
    const int wn   = warp & 3;
    const int t0   = blockIdx.y * 128;
    const int e0   = blockIdx.x * 128;

    float acc[4][4][4];
#pragma unroll
    for (int a = 0; a < 4; a++)
#pragma unroll
        for (int bq = 0; bq < 4; bq++)
#pragma unroll
            for (int c = 0; c < 4; c++) acc[a][bq][c] = 0.f;

    auto load_chunk = [&](int ch, int buf) {
        const __nv_bfloat16* s0 = g_xh + (size_t)t0 * D_MODEL + ch * 32;
        const __nv_bfloat16* s1 = g_xl + (size_t)t0 * D_MODEL + ch * 32;
        const __nv_bfloat16* s2 = g_wh + (size_t)e0 * D_MODEL + ch * 32;
        const __nv_bfloat16* s3 = g_wl + (size_t)e0 * D_MODEL + ch * 32;
        const __nv_bfloat16* srcs[4] = {s0, s1, s2, s3};
        const uint32_t bb = sb + buf * GBUFB;
#pragma unroll
        for (int u = 0; u < 8; u++) {
            const int idx = tid + u * 256;
            const int t   = idx >> 9;
            const int r   = idx & 511;
            const int row = r >> 2;
            const int seg = r & 3;
            CP_ASYNC16(bb + t * GTILEB + row * 80 + seg * 16,
                       srcs[t] + (size_t)row * D_MODEL + seg * 8);
        }
    };

    load_chunk(0, 0);
    CP_COMMIT();

    for (int it = 0; it < G_NCH; it++) {
        const int buf = it & 1;
        if (it + 1 < G_NCH) {
            load_chunk(it + 1, buf ^ 1);
            CP_COMMIT();
            CP_WAIT1();
        } else {
            CP_WAIT0();
        }
        __syncthreads();

        const uint32_t* Ah = (const uint32_t*)(smg + buf * GBUFB);
        const uint32_t* Al = Ah + GTILEB / 4;
        const uint32_t* Bh = Al + GTILEB / 4;
        const uint32_t* Bl = Bh + GTILEB / 4;

#pragma unroll
        for (int ks = 0; ks < 2; ks++) {
            const int kb = ks * 8 + tig;
            uint32_t ah[4][4], al[4][4];
#pragma unroll
            for (int mi = 0; mi < 4; mi++) {
                const int m0 = (wm * 64 + mi * 16 + g) * GROW32;
                ah[mi][0] = Ah[m0 + kb];
                ah[mi][1] = Ah[m0 + 8 * GROW32 + kb];
                ah[mi][2] = Ah[m0 + kb + 4];
                ah[mi][3] = Ah[m0 + 8 * GROW32 + kb + 4];
                al[mi][0] = Al[m0 + kb];
                al[mi][1] = Al[m0 + 8 * GROW32 + kb];
                al[mi][2] = Al[m0 + kb + 4];
                al[mi][3] = Al[m0 + 8 * GROW32 + kb + 4];
            }
#pragma unroll
            for (int ni = 0; ni < 4; ni++) {
                const int n0 = (wn * 32 + ni * 8 + g) * GROW32;
                uint32_t bh[2], bl[2];
                bh[0] = Bh[n0 + kb];
                bh[1] = Bh[n0 + kb + 4];
                bl[0] = Bl[n0 + kb];
                bl[1] = Bl[n0 + kb + 4];
#pragma unroll
                for (int mi = 0; mi < 4; mi++) {
                    mma_bf16(acc[mi][ni], ah[mi], bh);
                    mma_bf16(acc[mi][ni], al[mi], bh);
                    mma_bf16(acc[mi][ni], ah[mi], bl);
                }
            }
        }
        __syncthreads();
    }

#pragma unroll
    for (int mi = 0; mi < 4; mi++) {
        const int m = t0 + wm * 64 + mi * 16 + g;
#pragma unroll
        for (int ni = 0; ni < 4; ni++) {
            const int e = e0 + wn * 32 + ni * 8 + 2 * tig;
            const float b0 = bias[e], b1 = bias[e + 1];
            float2 r0, r1;
            r0.x = acc[mi][ni][0] + b0;
            r0.y = acc[mi][ni][1] + b1;
            r1.x = acc[mi][ni][2] + b0;
            r1.y = acc[mi][ni][3] + b1;
            *(float2*)&g_z[(size_t)m * EDIM + e]       = r0;
            *(float2*)&g_z[(size_t)(m + 8) * EDIM + e] = r1;
        }
    }
}

// ---------------------------------------------------------------------------
// Kernel 1b: transpose + bf16-split the V third of z.
// g_z[t][2048+e'] -> g_vth/g_vtl[e'][t].  32x32 smem tile transpose.
// ---------------------------------------------------------------------------
__global__ __launch_bounds__(256) void vtrans_k() {
    __shared__ float tile[32][33];
    const int tx = threadIdx.x & 31;
    const int ty = threadIdx.x >> 5;          // 0..7
    const int t0 = blockIdx.x * 32;
    const int e0 = blockIdx.y * 32;

#pragma unroll
    for (int i = 0; i < 4; i++)
        tile[ty + 8 * i][tx] = g_z[(size_t)(t0 + ty + 8 * i) * EDIM + 2 * D_MODEL + e0 + tx];
    __syncthreads();

#pragma unroll
    for (int i = 0; i < 4; i++) {
        const float v = tile[tx][ty + 8 * i];
        const __nv_bfloat16 hv = __float2bfloat16(v);
        const __nv_bfloat16 lv = __float2bfloat16(v - __bfloat162float(hv));
        const size_t o = (size_t)(e0 + ty + 8 * i) * TOK + t0 + tx;
        g_vth[o] = hv;
        g_vtl[o] = lv;
    }
}

// ---------------------------------------------------------------------------
// Kernel 2: tensor-core flash attention.
// K: fp32 cp.async double-buffered. V: bf16 hi/lo cp.async double-buffered
// from pre-transposed g_vth/g_vtl (zero in-kernel conversion work).
// ---------------------------------------------------------------------------
#define PAD   76
#define KVF   (64 * PAD)
#define OFF_K0 0
#define OFF_K1 (KVF)
#define VTROW  44                       // u32 per V col row (176B: 16B-aligned, conflict-free)
#define VTU    (64 * VTROW)             // 2816 u32 per (hi|lo) array
#define OFF_VT (2 * KVF)                // u32 index base; per buf: [Vth][Vtl]
#define ATTN_SMEM_BYTES ((2 * KVF + 4 * VTU) * 4)

__global__ __launch_bounds__(256, 2) void attn_tc(float* __restrict__ out) {
    extern __shared__ float sm[];
    uint32_t* smu = (uint32_t*)sm;
    const uint32_t sbb = smem_u32(sm);

    const int qb   = (int)gridDim.x - 1 - (int)blockIdx.x;
    const int h    = blockIdx.y;
    const int n    = blockIdx.z;
    const int tid  = threadIdx.x;
    const int lane = tid & 31;
    const int warp = tid >> 5;
    const int g    = lane >> 2;
    const int tig  = lane & 3;

    const int i0 = qb * 128 + warp * 16;
    const float scale = 1.0f / 32.0f;

    uint32_t qa[8][4];
    {
        const float* zq = &g_z[((size_t)(n * CTX)) * EDIM + D_MODEL + h * HD];
        const float* r0 = &zq[(size_t)(i0 + g) * EDIM];
        const float* r1 = &zq[(size_t)(i0 + g + 8) * EDIM];
#pragma unroll
        for (int ks = 0; ks < 8; ks++) {
            qa[ks][0] = cvt_rna_tf32(r0[ks * 8 + tig] * scale);
            qa[ks][1] = cvt_rna_tf32(r1[ks * 8 + tig] * scale);
            qa[ks][2] = cvt_rna_tf32(r0[ks * 8 + tig + 4] * scale);
            qa[ks][3] = cvt_rna_tf32(r1[ks * 8 + tig + 4] * scale);
        }
    }

    float oacc[8][4];
#pragma unroll
    for (int nt = 0; nt < 8; nt++)
#pragma unroll
        for (int c = 0; c < 4; c++) oacc[nt][c] = 0.f;
    float m0 = -1e30f, m1 = -1e30f, l0 = 0.f, l1 = 0.f;

    const int ntiles   = qb * 2 + 2;
    const int my_tiles = qb * 2 + 1 + (warp >> 2);

    auto load_K = [&](int jt, int buf) {
        const float* zk = &g_z[((size_t)(n * CTX + jt * 64)) * EDIM + h * HD];
        float* Kd = &sm[buf ? OFF_K1 : OFF_K0];
#pragma unroll
        for (int u = 0; u < 4; u++) {
            const int idx = tid + u * 256;
            const int row = idx >> 4;
            const int c4  = (idx & 15) * 4;
            CP_ASYNC16(smem_u32(&Kd[row * PAD + c4]), &zk[(size_t)row * EDIM + c4]);
        }
    };
    auto load_V = [&](int jt, int buf) {
        const size_t base = (size_t)h * 64 * TOK + (size_t)n * CTX + jt * 64;
#pragma unroll
        for (int u = 0; u < 4; u++) {
            const int idx = tid + u * 256;       // 0..1023
            const int t   = idx >> 9;            // 0 = hi, 1 = lo
            const int r   = idx & 511;
            const int col = r >> 3;
            const int seg = r & 7;               // 8 tokens (16B) per seg
            const __nv_bfloat16* src =
                (t ? g_vtl : g_vth) + base + (size_t)col * TOK + seg * 8;
            CP_ASYNC16(sbb + (OFF_VT + buf * 2 * VTU + t * VTU + col * VTROW) * 4 + seg * 16,
                       src);
        }
    };

    load_K(0, 0);
    load_V(0, 0);
    CP_COMMIT();

    for (int jt = 0; jt < ntiles; jt++) {
        const int buf = jt & 1;

        __syncthreads();   // sync[A]: prev compute done -> buf^1 free for prefetch

        if (jt + 1 < ntiles) {
            load_K(jt + 1, buf ^ 1);
            load_V(jt + 1, buf ^ 1);
            CP_COMMIT();
            CP_WAIT1();
        } else {
            CP_WAIT0();
        }
        __syncthreads();   // sync[B]: tile jt data visible to all warps

        if (jt < my_tiles) {
            const float* Ks = &sm[buf ? OFF_K1 : OFF_K0];
            const uint32_t* Vth = smu + OFF_VT + buf * 2 * VTU;
            const uint32_t* Vtl = Vth + VTU;

            // ---- S = Q K^T ----
            float sc[8][4];
#pragma unroll
            for (int nt = 0; nt < 8; nt++) {
                float a4[4] = {0.f, 0.f, 0.f, 0.f};
#pragma unroll
                for (int ks = 0; ks < 8; ks++) {
                    uint32_t b[2];
                    b[0] = __float_as_uint(Ks[(nt * 8 + g) * PAD + ks * 8 + tig]) & 0xffffe000u;
                    b[1] = __float_as_uint(Ks[(nt * 8 + g) * PAD + ks * 8 + tig + 4]) & 0xffffe000u;
                    mma_tf32(a4, qa[ks], b);
                }
                sc[nt][0] = a4[0]; sc[nt][1] = a4[1]; sc[nt][2] = a4[2]; sc[nt][3] = a4[3];
            }

            if (jt == my_tiles - 1) {
                const int r0 = i0 + g, r1 = i0 + g + 8;
#pragma unroll
                for (int nt = 0; nt < 8; nt++) {
                    const int j = jt * 64 + nt * 8 + 2 * tig;
                    if (j     > r0) sc[nt][0] = -INFINITY;
                    if (j + 1 > r0) sc[nt][1] = -INFINITY;
                    if (j     > r1) sc[nt][2] = -INFINITY;
                    if (j + 1 > r1) sc[nt][3] = -INFINITY;
                }
            }

            // ---- online softmax ----
            float mx0 = -INFINITY, mx1 = -INFINITY;
#pragma unroll
            for (int nt = 0; nt < 8; nt++) {
                mx0 = fmaxf(mx0, fmaxf(sc[nt][0], sc[nt][1]));
                mx1 = fmaxf(mx1, fmaxf(sc[nt][2], sc[nt][3]));
            }
            mx0 = fmaxf(mx0, __shfl_xor_sync(0xffffffffu, mx0, 1));
            mx0 = fmaxf(mx0, __shfl_xor_sync(0xffffffffu, mx0, 2));
            mx1 = fmaxf(mx1, __shfl_xor_sync(0xffffffffu, mx1, 1));
            mx1 = fmaxf(mx1, __shfl_xor_sync(0xffffffffu, mx1, 2));

            const float mn0 = fmaxf(m0, mx0);
            const float mn1 = fmaxf(m1, mx1);
            const float c0 = __expf(m0 - mn0);
            const float c1 = __expf(m1 - mn1);
            m0 = mn0; m1 = mn1;

            float rs0 = 0.f, rs1 = 0.f;
#pragma unroll
            for (int nt = 0; nt < 8; nt++) {
                sc[nt][0] = __expf(sc[nt][0] - mn0);
                sc[nt][1] = __expf(sc[nt][1] - mn0);
                sc[nt][2] = __expf(sc[nt][2] - mn1);
                sc[nt][3] = __expf(sc[nt][3] - mn1);
                rs0 += sc[nt][0] + sc[nt][1];
                rs1 += sc[nt][2] + sc[nt][3];
            }
            rs0 += __shfl_xor_sync(0xffffffffu, rs0, 1);
            rs0 += __shfl_xor_sync(0xffffffffu, rs0, 2);
            rs1 += __shfl_xor_sync(0xffffffffu, rs1, 1);
            rs1 += __shfl_xor_sync(0xffffffffu, rs1, 2);
            l0 = l0 * c0 + rs0;
            l1 = l1 * c1 + rs1;

#pragma unroll
            for (int nt = 0; nt < 8; nt++) {
                oacc[nt][0] *= c0; oacc[nt][1] *= c0;
                oacc[nt][2] *= c1; oacc[nt][3] *= c1;
            }

            // ---- O += P V (bf16x2 3-mma; V frags = 2x LDS.32, pre-split) ----
#pragma unroll
            for (int ks = 0; ks < 4; ks++) {
                uint32_t ah[4], al[4];
                split_bf16x2(sc[2 * ks][0],     sc[2 * ks][1],     ah[0], al[0]);
                split_bf16x2(sc[2 * ks][2],     sc[2 * ks][3],     ah[1], al[1]);
                split_bf16x2(sc[2 * ks + 1][0], sc[2 * ks + 1][1], ah[2], al[2]);
                split_bf16x2(sc[2 * ks + 1][2], sc[2 * ks + 1][3], ah[3], al[3]);
#pragma unroll
                for (int nt = 0; nt < 8; nt++) {
                    const uint32_t* vh = &Vth[(nt * 8 + g) * VTROW + 8 * ks + tig];
                    const uint32_t* vl = &Vtl[(nt * 8 + g) * VTROW + 8 * ks + tig];
                    uint32_t bh[2] = {vh[0], vh[4]};
                    uint32_t bl[2] = {vl[0], vl[4]};
                    mma_bf16(oacc[nt], ah, bh);
                    mma_bf16(oacc[nt], al, bh);
                    mma_bf16(oacc[nt], ah, bl);
                }
            }
        }
    }

    const float inv0 = 1.f / l0;
    const float inv1 = 1.f / l1;
    float* o0 = &out[((size_t)(n * CTX + i0 + g))     * D_MODEL + h * HD];
    float* o1 = &out[((size_t)(n * CTX + i0 + g + 8)) * D_MODEL + h * HD];
#pragma unroll
    for (int nt = 0; nt < 8; nt++) {
        *(float2*)&o0[nt * 8 + 2 * tig] = make_float2(oacc[nt][0] * inv0, oacc[nt][1] * inv0);
        *(float2*)&o1[nt * 8 + 2 * tig] = make_float2(oacc[nt][2] * inv1, oacc[nt][3] * inv1);
    }
}

extern "C" void kernel_launch(void* const* d_in, const int* in_sizes, int n_in,
                              void* d_out, int out_size) {
    const float* x = (const float*)d_in[0];
    const float* W = (const float*)d_in[1];
    const float* b = (const float*)d_in[2];
    float* out = (float*)d_out;

    const int n4x = TOK * D_MODEL / 4;
    const int n4w = EDIM * D_MODEL / 4;
    presplit_k<<<(n4x + 255) / 256, 256>>>(x, 0, n4x);
    presplit_k<<<(n4w + 255) / 256, 256>>>(W, 1, n4w);

    cudaFuncSetAttribute(qkv_gemm_bf, cudaFuncAttributeMaxDynamicSharedMemorySize,
                         GEMM_SMEM_BYTES);
    dim3 g1(EDIM / 128, TOK / 128);
    qkv_gemm_bf<<<g1, 256, GEMM_SMEM_BYTES>>>(b);

    dim3 gt(TOK / 32, D_MODEL / 32);
    vtrans_k<<<gt, 256>>>();

    cudaFuncSetAttribute(attn_tc, cudaFuncAttributeMaxDynamicSharedMemorySize,
                         ATTN_SMEM_BYTES);
    dim3 g2(CTX / 128, NHEADS, NB);
    attn_tc<<<g2, 256, ATTN_SMEM_BYTES>>>(out);
}